// round 10
// baseline (speedup 1.0000x reference)
#include <cuda_runtime.h>
#include <math.h>
#include <stdint.h>

#define NN 32768
#define DD 256
#define KK 4096
#define OUT_SCALAR_BASE (NN * DD)
#define OUT_IDX_BASE    (NN * DD + 3)
#define CAP 28
#define EPSC 0.00390625f      // 2^-8 (4x margin over 2*2^-10 tf32 bound)
#define EPSA 1.5e-4f          // covers 2*ulp(256) + mma chain rounding
#define SMEMA 131072          // A resident: 8 sub-chunks * 128 rows * 32 tf32
#define SMEMB 32768           // one B 64-dim chunk (2 sub-chunks)
#define SMEM_DYN (SMEMA + 2 * SMEMB)

__device__ float    g_xx[NN];
__device__ float    g_s2[NN];
__device__ float    g_ee[KK];
__device__ unsigned g_emaxb;
__device__ int      g_idx[NN];
__device__ int      g_cnt[KK];
__device__ double   g_sq;
__device__ unsigned g_XT[(size_t)NN * DD];   // tf32(2x)
__device__ unsigned g_ET[(size_t)KK * DD];   // tf32(e)
__device__ int      g_cand[(size_t)NN * CAP];
__device__ int      g_ccnt[NN];

// ---- helpers ----
__device__ __forceinline__ uint32_t smem_u32(const void* p) {
    uint32_t a;
    asm("{ .reg .u64 t; cvta.to.shared.u64 t, %1; cvt.u32.u64 %0, t; }" : "=r"(a) : "l"(p));
    return a;
}
__device__ __forceinline__ void cp16(uint32_t dst, const void* src) {
    uint64_t gs;
    asm("cvta.to.global.u64 %0, %1;" : "=l"(gs) : "l"(src));
    asm volatile("cp.async.cg.shared.global [%0], [%1], 16;" :: "r"(dst), "l"(gs));
}
#define CP_COMMIT() asm volatile("cp.async.commit_group;" ::: "memory")
#define CP_WAIT0()  asm volatile("cp.async.wait_group 0;" ::: "memory")
__device__ __forceinline__ void ldsm4(uint32_t a, uint32_t& r0, uint32_t& r1,
                                      uint32_t& r2, uint32_t& r3) {
    asm volatile("ldmatrix.sync.aligned.m8n8.x4.shared.b16 {%0,%1,%2,%3}, [%4];"
                 : "=r"(r0), "=r"(r1), "=r"(r2), "=r"(r3) : "r"(a));
}
__device__ __forceinline__ void mma8(float* c, const uint32_t* a, uint32_t b0, uint32_t b1) {
    asm volatile("mma.sync.aligned.m16n8k8.row.col.f32.tf32.tf32.f32 "
                 "{%0,%1,%2,%3}, {%4,%5,%6,%7}, {%8,%9}, {%0,%1,%2,%3};"
                 : "+f"(c[0]), "+f"(c[1]), "+f"(c[2]), "+f"(c[3])
                 : "r"(a[0]), "r"(a[1]), "r"(a[2]), "r"(a[3]), "r"(b0), "r"(b1));
}
__device__ __forceinline__ unsigned tf32rna(float f) {
    unsigned u;
    asm("cvt.rna.tf32.f32 %0, %1;" : "=r"(u) : "f"(f));
    return u;
}

// ---- init ----
__global__ void k_init() {
    int i = blockIdx.x * blockDim.x + threadIdx.x;
    if (i < KK) g_cnt[i] = 0;
    if (i == 0) { g_sq = 0.0; g_emaxb = 0u; }
}

// ---- prep x: exact xx (reference chain), S2, tf32(2x) ----
__global__ void k_prep_x(const float* __restrict__ x) {
    int gw = (blockIdx.x * blockDim.x + threadIdx.x) >> 5, lane = threadIdx.x & 31;
    if (gw >= NN) return;
    const float* p = x + (size_t)gw * DD;
    float s = 0.f, s2 = 0.f;
#pragma unroll
    for (int j = 0; j < 8; j++) {
        float t = p[lane + 32 * j];
        s  = __fadd_rn(s, __fmul_rn(t, t));
        s2 += fabsf(t);
        g_XT[(size_t)gw * DD + lane + 32 * j] = tf32rna(2.0f * t);
    }
#pragma unroll
    for (int off = 16; off; off >>= 1) {
        s  = __fadd_rn(s, __shfl_xor_sync(0xffffffffu, s, off));
        s2 += __shfl_xor_sync(0xffffffffu, s2, off);
    }
    if (lane == 0) { g_xx[gw] = s; g_s2[gw] = 2.0f * s2; }
}

// ---- prep e: exact ee, global max|e|, tf32(e) ----
__global__ void k_prep_e(const float* __restrict__ emb) {
    int gw = (blockIdx.x * blockDim.x + threadIdx.x) >> 5, lane = threadIdx.x & 31;
    if (gw >= KK) return;
    const float* p = emb + (size_t)gw * DD;
    float s = 0.f, m = 0.f;
#pragma unroll
    for (int j = 0; j < 8; j++) {
        float t = p[lane + 32 * j];
        s = __fadd_rn(s, __fmul_rn(t, t));
        m = fmaxf(m, fabsf(t));
        g_ET[(size_t)gw * DD + lane + 32 * j] = tf32rna(t);
    }
#pragma unroll
    for (int off = 16; off; off >>= 1) {
        s = __fadd_rn(s, __shfl_xor_sync(0xffffffffu, s, off));
        m = fmaxf(m, __shfl_xor_sync(0xffffffffu, m, off));
    }
    if (lane == 0) { g_ee[gw] = s; atomicMax(&g_emaxb, __float_as_uint(m)); }
}

// ---- B 64-dim chunk load: tile t=(g>>2), c=(g&3); 2 sub-chunks of 128x32 ----
__device__ __forceinline__ void bload(uint32_t sB, int g, int tid) {
    const int t = g >> 2, c = g & 3;
    const uint32_t base = sB + (g & 1) * SMEMB;
    const unsigned* src = &g_ET[(size_t)(t * 128) * DD + c * 64];
#pragma unroll
    for (int i = 0; i < 8; i++) {
        int unit = i * 256 + tid;
        int h = unit >> 10, n = (unit >> 3) & 127, u = unit & 7;
        cp16(base + h * 16384 + n * 128 + ((u ^ (n & 7)) << 4),
             src + (size_t)n * DD + h * 32 + u * 4);
    }
}

// ---- fragment bundle: one k8 stage of A(32 rows) + B(64 cols) ----
struct Frag { uint32_t a0[4], a1[4], b[4][4]; };

__device__ __forceinline__ void ldstage(Frag& f, uint32_t sA, uint32_t bCh,
                                        int c, int s, int rA0, int uqA,
                                        int nB0, int uqB) {
    const uint32_t aCh = sA + (c * 2 + (s >> 2)) * 16384;
    const uint32_t bSc = bCh + (s >> 2) * 16384;
    const int us = (s & 3) * 2;
    {
        int u = us + uqA;
        ldsm4(aCh + rA0 * 128 + ((u ^ (rA0 & 7)) << 4), f.a0[0], f.a0[1], f.a0[2], f.a0[3]);
        int r1 = rA0 + 16;
        ldsm4(aCh + r1 * 128 + ((u ^ (r1 & 7)) << 4), f.a1[0], f.a1[1], f.a1[2], f.a1[3]);
    }
#pragma unroll
    for (int jp = 0; jp < 4; jp++) {
        int n = nB0 + jp * 16;
        int u = us + uqB;
        ldsm4(bSc + n * 128 + ((u ^ (n & 7)) << 4),
              f.b[jp][0], f.b[jp][1], f.b[jp][2], f.b[jp][3]);
    }
}

// ---- tf32 mma GEMM + epsilon filter ----
__global__ __launch_bounds__(256, 1) void k_mma() {
    extern __shared__ __align__(128) char dsm[];
    __shared__ float    ees[128];
    __shared__ unsigned rmin[128];
    __shared__ int      scnt[128];

    const int tid = threadIdx.x, lane = tid & 31, wid = tid >> 5;
    const int wm = wid & 3, wn = wid >> 2;
    const int row0 = blockIdx.x * 128;
    const uint32_t sA = smem_u32(dsm);
    const uint32_t sB = sA + SMEMA;
    const float emax = __uint_as_float(g_emaxb);

    if (tid < 128) { rmin[tid] = 0x7F7FFFFFu; scnt[tid] = 0; }

    // A resident: 8192 16B units, 8 sub-chunks of (128 rows x 32 dims)
#pragma unroll
    for (int i = 0; i < 32; i++) {
        int unit = tid + i * 256;
        int sc = unit >> 10, r = (unit >> 3) & 127, u = unit & 7;
        cp16(sA + sc * 16384 + r * 128 + ((u ^ (r & 7)) << 4),
             &g_XT[(size_t)(row0 + r) * DD + sc * 32 + u * 4]);
    }
    bload(sB, 0, tid);
    CP_COMMIT();

    // ldmatrix lane constants
    const int lrow = lane & 7, q = lane >> 3;
    const int rA0 = wm * 32 + ((q & 1) << 3) + lrow;
    const int uqA = q >> 1;
    const int nB0 = wn * 64 + ((q >> 1) << 3) + lrow;
    const int uqB = q & 1;
    const int rbase = wm * 32 + (lane >> 2);
    const int colb  = wn * 64 + ((lane & 3) << 1);
    float xr[4], epsr[4];
#pragma unroll
    for (int s = 0; s < 4; s++) {
        xr[s]   = g_xx[row0 + rbase + s * 8];
        epsr[s] = EPSC * g_s2[row0 + rbase + s * 8] * emax + EPSA;
    }

    float acc[2][8][4];
#pragma unroll
    for (int i = 0; i < 2; i++)
#pragma unroll
        for (int j = 0; j < 8; j++)
#pragma unroll
            for (int p = 0; p < 4; p++) acc[i][j][p] = 0.f;

    Frag fr[2];

#pragma unroll 1
    for (int t = 0; t < 32; t++) {
#pragma unroll
        for (int c = 0; c < 4; c++) {
            const int g = t * 4 + c;
            // 1 barrier per chunk: publishes chunk g AND retires buffer g-1
            CP_WAIT0();
            __syncthreads();
            if (g + 1 < 128) { bload(sB, g + 1, tid); CP_COMMIT(); }
            if (c == 0 && tid < 128) ees[tid] = g_ee[t * 128 + tid];

            const uint32_t bCh = sB + (g & 1) * SMEMB;
            // software-pipelined stages: LDSM for s+1 issued before MMAs of s
            ldstage(fr[0], sA, bCh, c, 0, rA0, uqA, nB0, uqB);
#pragma unroll
            for (int s = 0; s < 8; s++) {
                if (s < 7)
                    ldstage(fr[(s + 1) & 1], sA, bCh, c, s + 1, rA0, uqA, nB0, uqB);
                Frag& f = fr[s & 1];
#pragma unroll
                for (int jp = 0; jp < 4; jp++) {
                    mma8(acc[0][jp * 2],     f.a0, f.b[jp][0], f.b[jp][1]);
                    mma8(acc[0][jp * 2 + 1], f.a0, f.b[jp][2], f.b[jp][3]);
                    mma8(acc[1][jp * 2],     f.a1, f.b[jp][0], f.b[jp][1]);
                    mma8(acc[1][jp * 2 + 1], f.a1, f.b[jp][2], f.b[jp][3]);
                }
            }
        }

        // ---- barrier-free tile epilogue ----
        {
            float lm[4] = {3.4e38f, 3.4e38f, 3.4e38f, 3.4e38f};
#pragma unroll
            for (int i = 0; i < 2; i++)
#pragma unroll
                for (int j = 0; j < 8; j++)
#pragma unroll
                    for (int p = 0; p < 4; p++) {
                        int slot = i * 2 + (p >> 1);
                        float dd = (xr[slot] + ees[colb + j * 8 + (p & 1)]) - acc[i][j][p];
                        lm[slot] = fminf(lm[slot], dd);
                    }
            // quad-reduce row min across the 4 threads sharing each row
#pragma unroll
            for (int s = 0; s < 4; s++) {
                lm[s] = fminf(lm[s], __shfl_xor_sync(0xffffffffu, lm[s], 1));
                lm[s] = fminf(lm[s], __shfl_xor_sync(0xffffffffu, lm[s], 2));
            }
            float thr[4];
#pragma unroll
            for (int s = 0; s < 4; s++) {
                atomicMin(&rmin[rbase + s * 8], __float_as_uint(lm[s]));
                // unsynced read: any subset-min + eps is a valid (correct) threshold
                thr[s] = __uint_as_float(rmin[rbase + s * 8]) + epsr[s];
            }
#pragma unroll
            for (int i = 0; i < 2; i++)
#pragma unroll
                for (int j = 0; j < 8; j++)
#pragma unroll
                    for (int p = 0; p < 4; p++) {
                        int slot = i * 2 + (p >> 1);
                        float dd = (xr[slot] + ees[colb + j * 8 + (p & 1)]) - acc[i][j][p];
                        if (dd < thr[slot]) {
                            int rl = rbase + slot * 8;
                            int pos = atomicAdd(&scnt[rl], 1);
                            if (pos < CAP)
                                g_cand[(size_t)(row0 + rl) * CAP + pos] =
                                    t * 128 + colb + j * 8 + (p & 1);
                        }
                        acc[i][j][p] = 0.f;
                    }
        }
    }
    __syncthreads();
    if (tid < 128) g_ccnt[row0 + tid] = scnt[tid];
}

// ---- exact rescore (bit-exact reference chain) + fused histogram/idx out ----
__global__ void k_rescore(const float* __restrict__ x, const float* __restrict__ emb,
                          float* __restrict__ out) {
    int gw = (blockIdx.x * blockDim.x + threadIdx.x) >> 5, lane = threadIdx.x & 31;
    if (gw >= NN) return;
    int cnt = g_ccnt[gw];
    float xr = g_xx[gw];
    const float* xp = x + (size_t)gw * DD;
    unsigned long long best = ~0ull;
    if (cnt <= CAP) {
        for (int ci = lane; ci < cnt; ci += 32) {
            int k = g_cand[(size_t)gw * CAP + ci];
            const float* ep = emb + (size_t)k * DD;
            float acc = 0.f;
            for (int i = 0; i < DD; i++)
                acc = __fmaf_rn(2.0f * xp[i], ep[i], acc);
            float dd = __fadd_rn(__fadd_rn(xr, g_ee[k]), -acc);
            unsigned long long pk =
                (((unsigned long long)__float_as_uint(dd)) << 32) | (unsigned)k;
            if (pk < best) best = pk;
        }
    } else {                                       // overflow: exact full scan
        for (int k = lane; k < KK; k += 32) {
            const float* ep = emb + (size_t)k * DD;
            float acc = 0.f;
            for (int i = 0; i < DD; i++)
                acc = __fmaf_rn(2.0f * xp[i], ep[i], acc);
            float dd = __fadd_rn(__fadd_rn(xr, g_ee[k]), -acc);
            unsigned long long pk =
                (((unsigned long long)__float_as_uint(dd)) << 32) | (unsigned)k;
            if (pk < best) best = pk;
        }
    }
#pragma unroll
    for (int off = 16; off; off >>= 1) {
        unsigned long long o = __shfl_xor_sync(0xffffffffu, best, off);
        if (o < best) best = o;
    }
    if (lane == 0) {
        int c = (int)(best & 0xffffffffull);
        g_idx[gw] = c;
        atomicAdd(&g_cnt[c], 1);
        out[OUT_IDX_BASE + gw] = (float)c;
    }
}

// ---- gather + ST output + MSE (float4, identical per-element rounding) ----
__global__ void k_gather(const float* __restrict__ x, const float* __restrict__ emb,
                         const float* __restrict__ mask, float* __restrict__ out) {
    __shared__ double sh[8];
    double local = 0.0;
    const int n4 = NN * DD / 4;
    for (int id4 = blockIdx.x * blockDim.x + threadIdx.x; id4 < n4;
         id4 += gridDim.x * blockDim.x) {
        int row = id4 >> 6;
        float m = mask[row];
        float4 e4 = *(const float4*)&emb[(size_t)g_idx[row] * DD + (id4 & 63) * 4];
        float4 x4 = *(const float4*)&x[(size_t)id4 * 4];
        float4 o4;
        float qv, d1;
        qv = __fmul_rn(e4.x, m); d1 = __fadd_rn(qv, -x4.x); o4.x = __fadd_rn(x4.x, d1);
        local += (double)__fmul_rn(d1, d1);
        qv = __fmul_rn(e4.y, m); d1 = __fadd_rn(qv, -x4.y); o4.y = __fadd_rn(x4.y, d1);
        local += (double)__fmul_rn(d1, d1);
        qv = __fmul_rn(e4.z, m); d1 = __fadd_rn(qv, -x4.z); o4.z = __fadd_rn(x4.z, d1);
        local += (double)__fmul_rn(d1, d1);
        qv = __fmul_rn(e4.w, m); d1 = __fadd_rn(qv, -x4.w); o4.w = __fadd_rn(x4.w, d1);
        local += (double)__fmul_rn(d1, d1);
        *(float4*)&out[(size_t)id4 * 4] = o4;
    }
#pragma unroll
    for (int off = 16; off; off >>= 1) local += __shfl_xor_sync(0xffffffffu, local, off);
    int lane = threadIdx.x & 31, w = threadIdx.x >> 5;
    if (lane == 0) sh[w] = local;
    __syncthreads();
    if (threadIdx.x == 0) {
        double s = 0.0;
        for (int i = 0; i < (int)(blockDim.x >> 5); i++) s += sh[i];
        atomicAdd(&g_sq, s);
    }
}
__global__ void k_final(float* __restrict__ out) {
    __shared__ double sh[8];
    double local = 0.0;
    for (int k = threadIdx.x; k < KK; k += blockDim.x) {
        float p = __fmul_rn((float)g_cnt[k], 1.0f / 32768.0f);
        local += (double)__fmul_rn(p, logf(__fadd_rn(p, 1e-8f)));
    }
#pragma unroll
    for (int off = 16; off; off >>= 1) local += __shfl_xor_sync(0xffffffffu, local, off);
    int lane = threadIdx.x & 31, w = threadIdx.x >> 5;
    if (lane == 0) sh[w] = local;
    __syncthreads();
    if (threadIdx.x == 0) {
        double H = 0.0;
        for (int i = 0; i < (int)(blockDim.x >> 5); i++) H += sh[i];
        double mse = g_sq / (double)(NN * DD);
        float ql = (float)mse;
        out[OUT_SCALAR_BASE + 0] = __fmul_rn(0.25f, ql);
        out[OUT_SCALAR_BASE + 1] = ql;
        out[OUT_SCALAR_BASE + 2] = expf(-(float)H);
    }
}

extern "C" void kernel_launch(void* const* d_in, const int* in_sizes, int n_in,
                              void* d_out, int out_size) {
    const float* x    = (const float*)d_in[0];
    const float* emb  = (const float*)d_in[1];
    const float* mask = (const float*)d_in[2];
    float* out = (float*)d_out;

    cudaFuncSetAttribute(k_mma, cudaFuncAttributeMaxDynamicSharedMemorySize, SMEM_DYN);

    k_init<<<16, 256>>>();
    k_prep_x<<<(NN * 32) / 256, 256>>>(x);
    k_prep_e<<<(KK * 32) / 256, 256>>>(emb);
    k_mma<<<NN / 128, 256, SMEM_DYN>>>();
    k_rescore<<<(NN * 32) / 256, 256>>>(x, emb, out);
    k_gather<<<1024, 256>>>(x, emb, mask, out);
    k_final<<<1, 256>>>(out);
}

// round 11
// speedup vs baseline: 1.3516x; 1.3516x over previous
#include <cuda_runtime.h>
#include <cuda_fp16.h>
#include <math.h>
#include <stdint.h>

#define NN 32768
#define DD 256
#define KK 4096
#define OUT_SCALAR_BASE (NN * DD)
#define OUT_IDX_BASE    (NN * DD + 3)
#define CAP 28
#define EPSC 0.00390625f      // 2^-8: 4x margin over rigorous 2^-10 fp16 bound
#define EPSA 1.5e-4f          // covers 2*ulp(256) + fp32 accum chain
#define INV1024 9.765625e-4f  // exact 2^-10 (undo e prescale)
#define SMEMA 65536           // A resident: 4 sub-chunks * 128 rows * 64 fp16
#define SMEMB 65536           // one B full tile: 128 codes * 256 fp16
#define SMEM_DYN (SMEMA + 2 * SMEMB)

__device__ float    g_xx[NN];
__device__ float    g_s2[NN];
__device__ float    g_ee[KK];
__device__ unsigned g_emaxb;
__device__ int      g_idx[NN];
__device__ int      g_cnt[KK];
__device__ double   g_sq;
__device__ unsigned g_XH[(size_t)NN * 128];  // fp16(2x) pairs
__device__ unsigned g_EH[(size_t)KK * 128];  // fp16(1024*e) pairs
__device__ int      g_cand[(size_t)NN * CAP];
__device__ int      g_ccnt[NN];

// ---- helpers ----
__device__ __forceinline__ uint32_t smem_u32(const void* p) {
    uint32_t a;
    asm("{ .reg .u64 t; cvta.to.shared.u64 t, %1; cvt.u32.u64 %0, t; }" : "=r"(a) : "l"(p));
    return a;
}
__device__ __forceinline__ void cp16(uint32_t dst, const void* src) {
    uint64_t gs;
    asm("cvta.to.global.u64 %0, %1;" : "=l"(gs) : "l"(src));
    asm volatile("cp.async.cg.shared.global [%0], [%1], 16;" :: "r"(dst), "l"(gs));
}
#define CP_COMMIT() asm volatile("cp.async.commit_group;" ::: "memory")
#define CP_WAIT0()  asm volatile("cp.async.wait_group 0;" ::: "memory")
__device__ __forceinline__ void ldsm4(uint32_t a, uint32_t& r0, uint32_t& r1,
                                      uint32_t& r2, uint32_t& r3) {
    asm volatile("ldmatrix.sync.aligned.m8n8.x4.shared.b16 {%0,%1,%2,%3}, [%4];"
                 : "=r"(r0), "=r"(r1), "=r"(r2), "=r"(r3) : "r"(a));
}
__device__ __forceinline__ void mma16(float* c, const uint32_t* a, uint32_t b0, uint32_t b1) {
    asm volatile("mma.sync.aligned.m16n8k16.row.col.f32.f16.f16.f32 "
                 "{%0,%1,%2,%3}, {%4,%5,%6,%7}, {%8,%9}, {%0,%1,%2,%3};"
                 : "+f"(c[0]), "+f"(c[1]), "+f"(c[2]), "+f"(c[3])
                 : "r"(a[0]), "r"(a[1]), "r"(a[2]), "r"(a[3]), "r"(b0), "r"(b1));
}
__device__ __forceinline__ unsigned packh2(float a, float b) {
    unsigned lo = __half_as_ushort(__float2half_rn(a));
    unsigned hi = __half_as_ushort(__float2half_rn(b));
    return lo | (hi << 16);
}

// ---- init ----
__global__ void k_init() {
    int i = blockIdx.x * blockDim.x + threadIdx.x;
    if (i < KK) g_cnt[i] = 0;
    if (i == 0) { g_sq = 0.0; g_emaxb = 0u; }
}

// ---- prep x: exact xx (reference chain), S2, fp16(2x) ----
__global__ void k_prep_x(const float* __restrict__ x) {
    int gw = (blockIdx.x * blockDim.x + threadIdx.x) >> 5, lane = threadIdx.x & 31;
    if (gw >= NN) return;
    const float* p = x + (size_t)gw * DD;
    float s = 0.f, s2 = 0.f;
#pragma unroll
    for (int j = 0; j < 8; j++) {
        float t = p[lane + 32 * j];
        s  = __fadd_rn(s, __fmul_rn(t, t));
        s2 += fabsf(t);
    }
    const float2* p2 = (const float2*)p;
#pragma unroll
    for (int j = 0; j < 4; j++) {
        int id2 = lane + 32 * j;
        float2 v = p2[id2];
        g_XH[(size_t)gw * 128 + id2] = packh2(2.0f * v.x, 2.0f * v.y);
    }
#pragma unroll
    for (int off = 16; off; off >>= 1) {
        s  = __fadd_rn(s, __shfl_xor_sync(0xffffffffu, s, off));
        s2 += __shfl_xor_sync(0xffffffffu, s2, off);
    }
    if (lane == 0) { g_xx[gw] = s; g_s2[gw] = 2.0f * s2; }
}

// ---- prep e: exact ee, global max|e|, fp16(1024*e) ----
__global__ void k_prep_e(const float* __restrict__ emb) {
    int gw = (blockIdx.x * blockDim.x + threadIdx.x) >> 5, lane = threadIdx.x & 31;
    if (gw >= KK) return;
    const float* p = emb + (size_t)gw * DD;
    float s = 0.f, m = 0.f;
#pragma unroll
    for (int j = 0; j < 8; j++) {
        float t = p[lane + 32 * j];
        s = __fadd_rn(s, __fmul_rn(t, t));
        m = fmaxf(m, fabsf(t));
    }
    const float2* p2 = (const float2*)p;
#pragma unroll
    for (int j = 0; j < 4; j++) {
        int id2 = lane + 32 * j;
        float2 v = p2[id2];
        g_EH[(size_t)gw * 128 + id2] = packh2(1024.0f * v.x, 1024.0f * v.y);
    }
#pragma unroll
    for (int off = 16; off; off >>= 1) {
        s = __fadd_rn(s, __shfl_xor_sync(0xffffffffu, s, off));
        m = fmaxf(m, __shfl_xor_sync(0xffffffffu, m, off));
    }
    if (lane == 0) { g_ee[gw] = s; atomicMax(&g_emaxb, __float_as_uint(m)); }
}

// ---- B full-tile load: 128 codes x 256 fp16 = 4096 16B units, swizzled ----
__device__ __forceinline__ void bload(uint32_t sB, int t, int tid) {
    const uint32_t base = sB + (t & 1) * SMEMB;
    const unsigned* src = &g_EH[(size_t)(t * 128) * 128];
#pragma unroll
    for (int i = 0; i < 16; i++) {
        int idx = i * 256 + tid;
        int sc = idx >> 10, n = (idx >> 3) & 127, u = idx & 7;
        cp16(base + sc * 16384 + n * 128 + ((u ^ (n & 7)) << 4),
             src + (size_t)n * 128 + sc * 32 + u * 4);
    }
}

// ---- fragment bundle: one k16 stage of A(32 rows) + B(64 cols) ----
struct Frag { uint32_t a0[4], a1[4], b[4][4]; };

__device__ __forceinline__ void ldstage(Frag& f, uint32_t sA, uint32_t bBuf,
                                        int s, int rA0, int uqA, int nB0, int uqB) {
    const uint32_t aCh = sA + (s >> 2) * 16384;
    const uint32_t bSc = bBuf + (s >> 2) * 16384;
    const int us = (s & 3) * 2;
    {
        int u = us + uqA;
        ldsm4(aCh + rA0 * 128 + ((u ^ (rA0 & 7)) << 4), f.a0[0], f.a0[1], f.a0[2], f.a0[3]);
        int r1 = rA0 + 16;
        ldsm4(aCh + r1 * 128 + ((u ^ (r1 & 7)) << 4), f.a1[0], f.a1[1], f.a1[2], f.a1[3]);
    }
#pragma unroll
    for (int jp = 0; jp < 4; jp++) {
        int n = nB0 + jp * 16;
        int u = us + uqB;
        ldsm4(bSc + n * 128 + ((u ^ (n & 7)) << 4),
              f.b[jp][0], f.b[jp][1], f.b[jp][2], f.b[jp][3]);
    }
}

// ---- fp16 mma GEMM + epsilon filter ----
__global__ __launch_bounds__(256, 1) void k_mma() {
    extern __shared__ __align__(128) char dsm[];
    __shared__ float    ees[2][128];
    __shared__ unsigned rmin[128];
    __shared__ int      scnt[128];

    const int tid = threadIdx.x, lane = tid & 31, wid = tid >> 5;
    const int wm = wid & 3, wn = wid >> 2;
    const int row0 = blockIdx.x * 128;
    const uint32_t sA = smem_u32(dsm);
    const uint32_t sB = sA + SMEMA;
    const float emax = __uint_as_float(g_emaxb);

    if (tid < 128) {
        rmin[tid] = 0x7F7FFFFFu;
        scnt[tid] = 0;
        ees[0][tid] = g_ee[tid];    // tile 0 ees, published by barrier below
    }

    // A resident: 4096 16B units, 4 sub-chunks of (128 rows x 64 fp16)
#pragma unroll
    for (int i = 0; i < 16; i++) {
        int idx = tid + i * 256;
        int sc = idx >> 10, r = (idx >> 3) & 127, u = idx & 7;
        cp16(sA + sc * 16384 + r * 128 + ((u ^ (r & 7)) << 4),
             &g_XH[(size_t)(row0 + r) * 128 + sc * 32 + u * 4]);
    }
    bload(sB, 0, tid);
    CP_COMMIT();

    // ldmatrix lane constants
    const int lrow = lane & 7, q = lane >> 3;
    const int rA0 = wm * 32 + ((q & 1) << 3) + lrow;
    const int uqA = q >> 1;
    const int nB0 = wn * 64 + ((q >> 1) << 3) + lrow;
    const int uqB = q & 1;
    const int rbase = wm * 32 + (lane >> 2);
    const int colb  = wn * 64 + ((lane & 3) << 1);
    float xr[4], epsr[4];
#pragma unroll
    for (int s = 0; s < 4; s++) {
        xr[s]   = g_xx[row0 + rbase + s * 8];
        epsr[s] = EPSC * g_s2[row0 + rbase + s * 8] * emax + EPSA;
    }

    float acc[2][8][4];
#pragma unroll
    for (int i = 0; i < 2; i++)
#pragma unroll
        for (int j = 0; j < 8; j++)
#pragma unroll
            for (int p = 0; p < 4; p++) acc[i][j][p] = 0.f;

    Frag fr[2];

#pragma unroll 1
    for (int t = 0; t < 32; t++) {
        // one barrier per tile: publishes B tile t + ees[t&1], retires buffer (t+1)&1
        CP_WAIT0();
        __syncthreads();
        if (t + 1 < 32) {
            bload(sB, t + 1, tid);
            CP_COMMIT();
            if (tid < 128) ees[(t + 1) & 1][tid] = g_ee[(t + 1) * 128 + tid];
        }
        const uint32_t bBuf = sB + (t & 1) * SMEMB;
        const float* eev = ees[t & 1];

        // 16 k16 stages, fragment double-buffered
        ldstage(fr[0], sA, bBuf, 0, rA0, uqA, nB0, uqB);
#pragma unroll
        for (int s = 0; s < 16; s++) {
            if (s < 15)
                ldstage(fr[(s + 1) & 1], sA, bBuf, s + 1, rA0, uqA, nB0, uqB);
            Frag& f = fr[s & 1];
#pragma unroll
            for (int jp = 0; jp < 4; jp++) {
                mma16(acc[0][jp * 2],     f.a0, f.b[jp][0], f.b[jp][1]);
                mma16(acc[0][jp * 2 + 1], f.a0, f.b[jp][2], f.b[jp][3]);
                mma16(acc[1][jp * 2],     f.a1, f.b[jp][0], f.b[jp][1]);
                mma16(acc[1][jp * 2 + 1], f.a1, f.b[jp][2], f.b[jp][3]);
            }
        }

        // ---- barrier-free tile epilogue (acc scaled by 1024: undo exactly) ----
        {
            float lm[4] = {3.4e38f, 3.4e38f, 3.4e38f, 3.4e38f};
#pragma unroll
            for (int i = 0; i < 2; i++)
#pragma unroll
                for (int j = 0; j < 8; j++)
#pragma unroll
                    for (int p = 0; p < 4; p++) {
                        int slot = i * 2 + (p >> 1);
                        float dd = (xr[slot] + eev[colb + j * 8 + (p & 1)])
                                   - acc[i][j][p] * INV1024;
                        lm[slot] = fminf(lm[slot], dd);
                    }
#pragma unroll
            for (int s = 0; s < 4; s++) {
                lm[s] = fminf(lm[s], __shfl_xor_sync(0xffffffffu, lm[s], 1));
                lm[s] = fminf(lm[s], __shfl_xor_sync(0xffffffffu, lm[s], 2));
            }
            float thr[4];
#pragma unroll
            for (int s = 0; s < 4; s++) {
                atomicMin(&rmin[rbase + s * 8], __float_as_uint(lm[s]));
                // unsynced read: any subset-min + eps is a valid threshold
                thr[s] = __uint_as_float(rmin[rbase + s * 8]) + epsr[s];
            }
#pragma unroll
            for (int i = 0; i < 2; i++)
#pragma unroll
                for (int j = 0; j < 8; j++)
#pragma unroll
                    for (int p = 0; p < 4; p++) {
                        int slot = i * 2 + (p >> 1);
                        float dd = (xr[slot] + eev[colb + j * 8 + (p & 1)])
                                   - acc[i][j][p] * INV1024;
                        if (dd < thr[slot]) {
                            int rl = rbase + slot * 8;
                            int pos = atomicAdd(&scnt[rl], 1);
                            if (pos < CAP)
                                g_cand[(size_t)(row0 + rl) * CAP + pos] =
                                    t * 128 + colb + j * 8 + (p & 1);
                        }
                        acc[i][j][p] = 0.f;
                    }
        }
    }
    __syncthreads();
    if (tid < 128) g_ccnt[row0 + tid] = scnt[tid];
}

// ---- exact rescore (bit-exact reference chain) + fused histogram/idx out ----
__global__ void k_rescore(const float* __restrict__ x, const float* __restrict__ emb,
                          float* __restrict__ out) {
    int gw = (blockIdx.x * blockDim.x + threadIdx.x) >> 5, lane = threadIdx.x & 31;
    if (gw >= NN) return;
    int cnt = g_ccnt[gw];
    float xr = g_xx[gw];
    const float* xp = x + (size_t)gw * DD;
    unsigned long long best = ~0ull;
    if (cnt <= CAP) {
        for (int ci = lane; ci < cnt; ci += 32) {
            int k = g_cand[(size_t)gw * CAP + ci];
            const float* ep = emb + (size_t)k * DD;
            float acc = 0.f;
            for (int i = 0; i < DD; i++)
                acc = __fmaf_rn(2.0f * xp[i], ep[i], acc);
            float dd = __fadd_rn(__fadd_rn(xr, g_ee[k]), -acc);
            unsigned long long pk =
                (((unsigned long long)__float_as_uint(dd)) << 32) | (unsigned)k;
            if (pk < best) best = pk;
        }
    } else {                                       // overflow: exact full scan
        for (int k = lane; k < KK; k += 32) {
            const float* ep = emb + (size_t)k * DD;
            float acc = 0.f;
            for (int i = 0; i < DD; i++)
                acc = __fmaf_rn(2.0f * xp[i], ep[i], acc);
            float dd = __fadd_rn(__fadd_rn(xr, g_ee[k]), -acc);
            unsigned long long pk =
                (((unsigned long long)__float_as_uint(dd)) << 32) | (unsigned)k;
            if (pk < best) best = pk;
        }
    }
#pragma unroll
    for (int off = 16; off; off >>= 1) {
        unsigned long long o = __shfl_xor_sync(0xffffffffu, best, off);
        if (o < best) best = o;
    }
    if (lane == 0) {
        int c = (int)(best & 0xffffffffull);
        g_idx[gw] = c;
        atomicAdd(&g_cnt[c], 1);
        out[OUT_IDX_BASE + gw] = (float)c;
    }
}

// ---- gather + ST output + MSE (float4, identical per-element rounding) ----
__global__ void k_gather(const float* __restrict__ x, const float* __restrict__ emb,
                         const float* __restrict__ mask, float* __restrict__ out) {
    __shared__ double sh[8];
    double local = 0.0;
    const int n4 = NN * DD / 4;
    for (int id4 = blockIdx.x * blockDim.x + threadIdx.x; id4 < n4;
         id4 += gridDim.x * blockDim.x) {
        int row = id4 >> 6;
        float m = mask[row];
        float4 e4 = *(const float4*)&emb[(size_t)g_idx[row] * DD + (id4 & 63) * 4];
        float4 x4 = *(const float4*)&x[(size_t)id4 * 4];
        float4 o4;
        float qv, d1;
        qv = __fmul_rn(e4.x, m); d1 = __fadd_rn(qv, -x4.x); o4.x = __fadd_rn(x4.x, d1);
        local += (double)__fmul_rn(d1, d1);
        qv = __fmul_rn(e4.y, m); d1 = __fadd_rn(qv, -x4.y); o4.y = __fadd_rn(x4.y, d1);
        local += (double)__fmul_rn(d1, d1);
        qv = __fmul_rn(e4.z, m); d1 = __fadd_rn(qv, -x4.z); o4.z = __fadd_rn(x4.z, d1);
        local += (double)__fmul_rn(d1, d1);
        qv = __fmul_rn(e4.w, m); d1 = __fadd_rn(qv, -x4.w); o4.w = __fadd_rn(x4.w, d1);
        local += (double)__fmul_rn(d1, d1);
        *(float4*)&out[(size_t)id4 * 4] = o4;
    }
#pragma unroll
    for (int off = 16; off; off >>= 1) local += __shfl_xor_sync(0xffffffffu, local, off);
    int lane = threadIdx.x & 31, w = threadIdx.x >> 5;
    if (lane == 0) sh[w] = local;
    __syncthreads();
    if (threadIdx.x == 0) {
        double s = 0.0;
        for (int i = 0; i < (int)(blockDim.x >> 5); i++) s += sh[i];
        atomicAdd(&g_sq, s);
    }
}
__global__ void k_final(float* __restrict__ out) {
    __shared__ double sh[8];
    double local = 0.0;
    for (int k = threadIdx.x; k < KK; k += blockDim.x) {
        float p = __fmul_rn((float)g_cnt[k], 1.0f / 32768.0f);
        local += (double)__fmul_rn(p, logf(__fadd_rn(p, 1e-8f)));
    }
#pragma unroll
    for (int off = 16; off; off >>= 1) local += __shfl_xor_sync(0xffffffffu, local, off);
    int lane = threadIdx.x & 31, w = threadIdx.x >> 5;
    if (lane == 0) sh[w] = local;
    __syncthreads();
    if (threadIdx.x == 0) {
        double H = 0.0;
        for (int i = 0; i < (int)(blockDim.x >> 5); i++) H += sh[i];
        double mse = g_sq / (double)(NN * DD);
        float ql = (float)mse;
        out[OUT_SCALAR_BASE + 0] = __fmul_rn(0.25f, ql);
        out[OUT_SCALAR_BASE + 1] = ql;
        out[OUT_SCALAR_BASE + 2] = expf(-(float)H);
    }
}

extern "C" void kernel_launch(void* const* d_in, const int* in_sizes, int n_in,
                              void* d_out, int out_size) {
    const float* x    = (const float*)d_in[0];
    const float* emb  = (const float*)d_in[1];
    const float* mask = (const float*)d_in[2];
    float* out = (float*)d_out;

    cudaFuncSetAttribute(k_mma, cudaFuncAttributeMaxDynamicSharedMemorySize, SMEM_DYN);

    k_init<<<16, 256>>>();
    k_prep_x<<<(NN * 32) / 256, 256>>>(x);
    k_prep_e<<<(KK * 32) / 256, 256>>>(emb);
    k_mma<<<NN / 128, 256, SMEM_DYN>>>();
    k_rescore<<<(NN * 32) / 256, 256>>>(x, emb, out);
    k_gather<<<1024, 256>>>(x, emb, mask, out);
    k_final<<<1, 256>>>(out);
}

// round 13
// speedup vs baseline: 1.3716x; 1.0148x over previous
#include <cuda_runtime.h>
#include <cuda_fp16.h>
#include <math.h>
#include <stdint.h>

#define NN 32768
#define DD 256
#define KK 4096
#define OUT_SCALAR_BASE (NN * DD)
#define OUT_IDX_BASE    (NN * DD + 3)
#define CAP 28
#define EPSC 0.00390625f      // 2^-8: 4x margin over rigorous 2^-10 fp16 bound
#define EPSA 1.5e-4f          // covers 2*ulp(256) + fp32 accum chain
#define INV1024 9.765625e-4f  // exact 2^-10 (undo e prescale)
#define SMEMA 65536           // A resident: 4 sub-chunks * 128 rows * 64 fp16
#define SMEMB 65536           // one B full tile: 128 codes * 256 fp16
#define SMEM_DYN (SMEMA + 2 * SMEMB)

__device__ float    g_xx[NN];
__device__ float    g_s2[NN];
__device__ float    g_ee[KK];
__device__ unsigned g_emaxb;
__device__ int      g_cnt[KK];
__device__ double   g_sq;
__device__ unsigned g_XH[(size_t)NN * 128];  // fp16(2x) pairs
__device__ unsigned g_EH[(size_t)KK * 128];  // fp16(1024*e) pairs
__device__ int      g_cand[(size_t)NN * CAP];
__device__ int      g_ccnt[NN];

// ---- helpers ----
__device__ __forceinline__ uint32_t smem_u32(const void* p) {
    uint32_t a;
    asm("{ .reg .u64 t; cvta.to.shared.u64 t, %1; cvt.u32.u64 %0, t; }" : "=r"(a) : "l"(p));
    return a;
}
__device__ __forceinline__ void cp16(uint32_t dst, const void* src) {
    uint64_t gs;
    asm("cvta.to.global.u64 %0, %1;" : "=l"(gs) : "l"(src));
    asm volatile("cp.async.cg.shared.global [%0], [%1], 16;" :: "r"(dst), "l"(gs));
}
#define CP_COMMIT() asm volatile("cp.async.commit_group;" ::: "memory")
#define CP_WAIT0()  asm volatile("cp.async.wait_group 0;" ::: "memory")
__device__ __forceinline__ void ldsm4(uint32_t a, uint32_t& r0, uint32_t& r1,
                                      uint32_t& r2, uint32_t& r3) {
    asm volatile("ldmatrix.sync.aligned.m8n8.x4.shared.b16 {%0,%1,%2,%3}, [%4];"
                 : "=r"(r0), "=r"(r1), "=r"(r2), "=r"(r3) : "r"(a));
}
__device__ __forceinline__ void mma16(float* c, const uint32_t* a, uint32_t b0, uint32_t b1) {
    asm volatile("mma.sync.aligned.m16n8k16.row.col.f32.f16.f16.f32 "
                 "{%0,%1,%2,%3}, {%4,%5,%6,%7}, {%8,%9}, {%0,%1,%2,%3};"
                 : "+f"(c[0]), "+f"(c[1]), "+f"(c[2]), "+f"(c[3])
                 : "r"(a[0]), "r"(a[1]), "r"(a[2]), "r"(a[3]), "r"(b0), "r"(b1));
}
__device__ __forceinline__ unsigned packh2(float a, float b) {
    unsigned lo = __half_as_ushort(__float2half_rn(a));
    unsigned hi = __half_as_ushort(__float2half_rn(b));
    return lo | (hi << 16);
}

// ---- init ----
__global__ void k_init() {
    int i = blockIdx.x * blockDim.x + threadIdx.x;
    if (i < KK) g_cnt[i] = 0;
    if (i == 0) { g_sq = 0.0; g_emaxb = 0u; }
}

// ---- prep x: exact xx (reference chain), S2, fp16(2x) ----
__global__ void k_prep_x(const float* __restrict__ x) {
    int gw = (blockIdx.x * blockDim.x + threadIdx.x) >> 5, lane = threadIdx.x & 31;
    if (gw >= NN) return;
    const float* p = x + (size_t)gw * DD;
    float s = 0.f, s2 = 0.f;
#pragma unroll
    for (int j = 0; j < 8; j++) {
        float t = p[lane + 32 * j];
        s  = __fadd_rn(s, __fmul_rn(t, t));
        s2 += fabsf(t);
    }
    const float2* p2 = (const float2*)p;
#pragma unroll
    for (int j = 0; j < 4; j++) {
        int id2 = lane + 32 * j;
        float2 v = p2[id2];
        g_XH[(size_t)gw * 128 + id2] = packh2(2.0f * v.x, 2.0f * v.y);
    }
#pragma unroll
    for (int off = 16; off; off >>= 1) {
        s  = __fadd_rn(s, __shfl_xor_sync(0xffffffffu, s, off));
        s2 += __shfl_xor_sync(0xffffffffu, s2, off);
    }
    if (lane == 0) { g_xx[gw] = s; g_s2[gw] = 2.0f * s2; }
}

// ---- prep e: exact ee, global max|e|, fp16(1024*e) ----
__global__ void k_prep_e(const float* __restrict__ emb) {
    int gw = (blockIdx.x * blockDim.x + threadIdx.x) >> 5, lane = threadIdx.x & 31;
    if (gw >= KK) return;
    const float* p = emb + (size_t)gw * DD;
    float s = 0.f, m = 0.f;
#pragma unroll
    for (int j = 0; j < 8; j++) {
        float t = p[lane + 32 * j];
        s = __fadd_rn(s, __fmul_rn(t, t));
        m = fmaxf(m, fabsf(t));
    }
    const float2* p2 = (const float2*)p;
#pragma unroll
    for (int j = 0; j < 4; j++) {
        int id2 = lane + 32 * j;
        float2 v = p2[id2];
        g_EH[(size_t)gw * 128 + id2] = packh2(1024.0f * v.x, 1024.0f * v.y);
    }
#pragma unroll
    for (int off = 16; off; off >>= 1) {
        s = __fadd_rn(s, __shfl_xor_sync(0xffffffffu, s, off));
        m = fmaxf(m, __shfl_xor_sync(0xffffffffu, m, off));
    }
    if (lane == 0) { g_ee[gw] = s; atomicMax(&g_emaxb, __float_as_uint(m)); }
}

// ---- B full-tile load: 128 codes x 256 fp16 = 4096 16B units, swizzled ----
__device__ __forceinline__ void bload(uint32_t sB, int t, int tid) {
    const uint32_t base = sB + (t & 1) * SMEMB;
    const unsigned* src = &g_EH[(size_t)(t * 128) * 128];
#pragma unroll
    for (int i = 0; i < 8; i++) {
        int idx = i * 512 + tid;
        int sc = idx >> 10, n = (idx >> 3) & 127, u = idx & 7;
        cp16(base + sc * 16384 + n * 128 + ((u ^ (n & 7)) << 4),
             src + (size_t)n * 128 + sc * 32 + u * 4);
    }
}

// ---- fragment bundle: one k16 stage of A(32 rows) + B(32 cols) ----
struct Frag { uint32_t a0[4], a1[4], b[2][4]; };

__device__ __forceinline__ void ldstage(Frag& f, uint32_t sA, uint32_t bBuf,
                                        int s, int rA0, int uqA, int nB0, int uqB) {
    const uint32_t aCh = sA + (s >> 2) * 16384;
    const uint32_t bSc = bBuf + (s >> 2) * 16384;
    const int us = (s & 3) * 2;
    {
        int u = us + uqA;
        ldsm4(aCh + rA0 * 128 + ((u ^ (rA0 & 7)) << 4), f.a0[0], f.a0[1], f.a0[2], f.a0[3]);
        int r1 = rA0 + 16;
        ldsm4(aCh + r1 * 128 + ((u ^ (r1 & 7)) << 4), f.a1[0], f.a1[1], f.a1[2], f.a1[3]);
    }
#pragma unroll
    for (int jp = 0; jp < 2; jp++) {
        int n = nB0 + jp * 16;
        int u = us + uqB;
        ldsm4(bSc + n * 128 + ((u ^ (n & 7)) << 4),
              f.b[jp][0], f.b[jp][1], f.b[jp][2], f.b[jp][3]);
    }
}

// ---- fp16 mma GEMM + epsilon filter (512 threads, warp tile 32x32) ----
__global__ __launch_bounds__(512, 1) void k_mma() {
    extern __shared__ __align__(128) char dsm[];
    __shared__ float    ees[2][128];
    __shared__ unsigned rmin[128];
    __shared__ int      scnt[128];

    const int tid = threadIdx.x, lane = tid & 31, wid = tid >> 5;
    const int wm = wid & 3, wn = wid >> 2;       // 4x4 warp grid
    const int row0 = blockIdx.x * 128;
    const uint32_t sA = smem_u32(dsm);
    const uint32_t sB = sA + SMEMA;
    const float emax = __uint_as_float(g_emaxb);

    if (tid < 128) {
        rmin[tid] = 0x7F7FFFFFu;
        scnt[tid] = 0;
        ees[0][tid] = g_ee[tid];    // tile 0 ees, published by barrier below
    }

    // A resident: 4096 16B units, 4 sub-chunks of (128 rows x 64 fp16)
#pragma unroll
    for (int i = 0; i < 8; i++) {
        int idx = tid + i * 512;
        int sc = idx >> 10, r = (idx >> 3) & 127, u = idx & 7;
        cp16(sA + sc * 16384 + r * 128 + ((u ^ (r & 7)) << 4),
             &g_XH[(size_t)(row0 + r) * 128 + sc * 32 + u * 4]);
    }
    bload(sB, 0, tid);
    CP_COMMIT();

    // ldmatrix lane constants
    const int lrow = lane & 7, q = lane >> 3;
    const int rA0 = wm * 32 + ((q & 1) << 3) + lrow;
    const int uqA = q >> 1;
    const int nB0 = wn * 32 + ((q >> 1) << 3) + lrow;
    const int uqB = q & 1;
    const int rbase = wm * 32 + (lane >> 2);
    const int colb  = wn * 32 + ((lane & 3) << 1);
    float xr[4], epsr[4];
#pragma unroll
    for (int s = 0; s < 4; s++) {
        xr[s]   = g_xx[row0 + rbase + s * 8];
        epsr[s] = EPSC * g_s2[row0 + rbase + s * 8] * emax + EPSA;
    }

    float acc[2][4][4];
#pragma unroll
    for (int i = 0; i < 2; i++)
#pragma unroll
        for (int j = 0; j < 4; j++)
#pragma unroll
            for (int p = 0; p < 4; p++) acc[i][j][p] = 0.f;

    Frag fr[2];

#pragma unroll 1
    for (int t = 0; t < 32; t++) {
        // one barrier per tile: publishes B tile t + ees[t&1], retires buffer (t+1)&1
        CP_WAIT0();
        __syncthreads();
        if (t + 1 < 32) {
            bload(sB, t + 1, tid);
            CP_COMMIT();
            if (tid < 128) ees[(t + 1) & 1][tid] = g_ee[(t + 1) * 128 + tid];
        }
        const uint32_t bBuf = sB + (t & 1) * SMEMB;
        const float* eev = ees[t & 1];

        // 16 k16 stages, fragment double-buffered
        ldstage(fr[0], sA, bBuf, 0, rA0, uqA, nB0, uqB);
#pragma unroll
        for (int s = 0; s < 16; s++) {
            if (s < 15)
                ldstage(fr[(s + 1) & 1], sA, bBuf, s + 1, rA0, uqA, nB0, uqB);
            Frag& f = fr[s & 1];
#pragma unroll
            for (int jp = 0; jp < 2; jp++) {
                mma16(acc[0][jp * 2],     f.a0, f.b[jp][0], f.b[jp][1]);
                mma16(acc[0][jp * 2 + 1], f.a0, f.b[jp][2], f.b[jp][3]);
                mma16(acc[1][jp * 2],     f.a1, f.b[jp][0], f.b[jp][1]);
                mma16(acc[1][jp * 2 + 1], f.a1, f.b[jp][2], f.b[jp][3]);
            }
        }

        // ---- barrier-free tile epilogue (acc scaled by 1024: undo exactly) ----
        {
            float lm[4] = {3.4e38f, 3.4e38f, 3.4e38f, 3.4e38f};
#pragma unroll
            for (int i = 0; i < 2; i++)
#pragma unroll
                for (int j = 0; j < 4; j++)
#pragma unroll
                    for (int p = 0; p < 4; p++) {
                        int slot = i * 2 + (p >> 1);
                        float dd = (xr[slot] + eev[colb + j * 8 + (p & 1)])
                                   - acc[i][j][p] * INV1024;
                        lm[slot] = fminf(lm[slot], dd);
                    }
#pragma unroll
            for (int s = 0; s < 4; s++) {
                lm[s] = fminf(lm[s], __shfl_xor_sync(0xffffffffu, lm[s], 1));
                lm[s] = fminf(lm[s], __shfl_xor_sync(0xffffffffu, lm[s], 2));
            }
            float thr[4];
#pragma unroll
            for (int s = 0; s < 4; s++) {
                atomicMin(&rmin[rbase + s * 8], __float_as_uint(lm[s]));
                // unsynced read: any subset-min + eps is a valid threshold
                thr[s] = __uint_as_float(rmin[rbase + s * 8]) + epsr[s];
            }
#pragma unroll
            for (int i = 0; i < 2; i++)
#pragma unroll
                for (int j = 0; j < 4; j++)
#pragma unroll
                    for (int p = 0; p < 4; p++) {
                        int slot = i * 2 + (p >> 1);
                        float dd = (xr[slot] + eev[colb + j * 8 + (p & 1)])
                                   - acc[i][j][p] * INV1024;
                        if (dd < thr[slot]) {
                            int rl = rbase + slot * 8;
                            int pos = atomicAdd(&scnt[rl], 1);
                            if (pos < CAP)
                                g_cand[(size_t)(row0 + rl) * CAP + pos] =
                                    t * 128 + colb + j * 8 + (p & 1);
                        }
                        acc[i][j][p] = 0.f;
                    }
        }
    }
    __syncthreads();
    if (tid < 128) g_ccnt[row0 + tid] = scnt[tid];
}

// ---- fused: exact rescore + gather + ST output + MSE + histogram ----
__global__ void k_finish(const float* __restrict__ x, const float* __restrict__ emb,
                         const float* __restrict__ mask, float* __restrict__ out) {
    __shared__ double sh[8];
    const int lane = threadIdx.x & 31, w = threadIdx.x >> 5;
    const int gw = blockIdx.x * 8 + w;

    // --- exact rescore over candidates (bit-exact reference chain) ---
    int cnt = g_ccnt[gw];
    float xr = g_xx[gw];
    const float* xp = x + (size_t)gw * DD;
    unsigned long long best = ~0ull;
    if (cnt <= CAP) {
        for (int ci = lane; ci < cnt; ci += 32) {
            int k = g_cand[(size_t)gw * CAP + ci];
            const float* ep = emb + (size_t)k * DD;
            float acc = 0.f;
            for (int i = 0; i < DD; i++)
                acc = __fmaf_rn(2.0f * xp[i], ep[i], acc);
            float dd = __fadd_rn(__fadd_rn(xr, g_ee[k]), -acc);
            unsigned long long pk =
                (((unsigned long long)__float_as_uint(dd)) << 32) | (unsigned)k;
            if (pk < best) best = pk;
        }
    } else {                                       // overflow: exact full scan
        for (int k = lane; k < KK; k += 32) {
            const float* ep = emb + (size_t)k * DD;
            float acc = 0.f;
            for (int i = 0; i < DD; i++)
                acc = __fmaf_rn(2.0f * xp[i], ep[i], acc);
            float dd = __fadd_rn(__fadd_rn(xr, g_ee[k]), -acc);
            unsigned long long pk =
                (((unsigned long long)__float_as_uint(dd)) << 32) | (unsigned)k;
            if (pk < best) best = pk;
        }
    }
#pragma unroll
    for (int off = 16; off; off >>= 1) {
        unsigned long long o = __shfl_xor_sync(0xffffffffu, best, off);
        if (o < best) best = o;
    }
    const int c = (int)(best & 0xffffffffull);     // all lanes hold the min
    if (lane == 0) {
        atomicAdd(&g_cnt[c], 1);
        out[OUT_IDX_BASE + gw] = (float)c;
    }

    // --- gather + straight-through output + MSE (identical rounding) ---
    const float m = mask[gw];
    const float4* e4p = (const float4*)(emb + (size_t)c * DD);
    const float4* x4p = (const float4*)(x + (size_t)gw * DD);
    float4* o4p = (float4*)(out + (size_t)gw * DD);
    double local = 0.0;
#pragma unroll
    for (int j = 0; j < 2; j++) {
        int i4 = lane + 32 * j;
        float4 e4 = e4p[i4], x4 = x4p[i4], o4;
        float qv, d1;
        qv = __fmul_rn(e4.x, m); d1 = __fadd_rn(qv, -x4.x); o4.x = __fadd_rn(x4.x, d1);
        local += (double)__fmul_rn(d1, d1);
        qv = __fmul_rn(e4.y, m); d1 = __fadd_rn(qv, -x4.y); o4.y = __fadd_rn(x4.y, d1);
        local += (double)__fmul_rn(d1, d1);
        qv = __fmul_rn(e4.z, m); d1 = __fadd_rn(qv, -x4.z); o4.z = __fadd_rn(x4.z, d1);
        local += (double)__fmul_rn(d1, d1);
        qv = __fmul_rn(e4.w, m); d1 = __fadd_rn(qv, -x4.w); o4.w = __fadd_rn(x4.w, d1);
        local += (double)__fmul_rn(d1, d1);
        o4p[i4] = o4;
    }
#pragma unroll
    for (int off = 16; off; off >>= 1) local += __shfl_xor_sync(0xffffffffu, local, off);
    if (lane == 0) sh[w] = local;
    __syncthreads();
    if (threadIdx.x == 0) {
        double s = 0.0;
        for (int i = 0; i < 8; i++) s += sh[i];
        atomicAdd(&g_sq, s);
    }
}

__global__ void k_final(float* __restrict__ out) {
    __shared__ double sh[8];
    double local = 0.0;
    for (int k = threadIdx.x; k < KK; k += blockDim.x) {
        float p = __fmul_rn((float)g_cnt[k], 1.0f / 32768.0f);
        local += (double)__fmul_rn(p, logf(__fadd_rn(p, 1e-8f)));
    }
#pragma unroll
    for (int off = 16; off; off >>= 1) local += __shfl_xor_sync(0xffffffffu, local, off);
    int lane = threadIdx.x & 31, w = threadIdx.x >> 5;
    if (lane == 0) sh[w] = local;
    __syncthreads();
    if (threadIdx.x == 0) {
        double H = 0.0;
        for (int i = 0; i < (int)(blockDim.x >> 5); i++) H += sh[i];
        double mse = g_sq / (double)(NN * DD);
        float ql = (float)mse;
        out[OUT_SCALAR_BASE + 0] = __fmul_rn(0.25f, ql);
        out[OUT_SCALAR_BASE + 1] = ql;
        out[OUT_SCALAR_BASE + 2] = expf(-(float)H);
    }
}

extern "C" void kernel_launch(void* const* d_in, const int* in_sizes, int n_in,
                              void* d_out, int out_size) {
    const float* x    = (const float*)d_in[0];
    const float* emb  = (const float*)d_in[1];
    const float* mask = (const float*)d_in[2];
    float* out = (float*)d_out;

    cudaFuncSetAttribute(k_mma, cudaFuncAttributeMaxDynamicSharedMemorySize, SMEM_DYN);

    k_init<<<16, 256>>>();
    k_prep_x<<<(NN * 32) / 256, 256>>>(x);
    k_prep_e<<<(KK * 32) / 256, 256>>>(emb);
    k_mma<<<NN / 128, 512, SMEM_DYN>>>();
    k_finish<<<NN / 8, 256>>>(x, emb, mask, out);
    k_final<<<1, 256>>>(out);
}

// round 14
// speedup vs baseline: 2.1298x; 1.5527x over previous
#include <cuda_runtime.h>
#include <cuda_fp16.h>
#include <math.h>
#include <stdint.h>

#define NN 32768
#define DD 256
#define KK 4096
#define OUT_SCALAR_BASE (NN * DD)
#define OUT_IDX_BASE    (NN * DD + 3)
#define CAP 28
#define EPSC 0.00390625f      // 2^-8: 4x margin over rigorous 2^-10 fp16 bound
#define EPSA 1.5e-4f          // covers 2*ulp(256) + fp32 accum chain
#define INV1024 9.765625e-4f  // exact 2^-10 (undo e prescale)
#define SMEMA 65536           // A resident: 4 sub-chunks * 128 rows * 64 fp16
#define SMEMB 65536           // one B full tile: 128 codes * 256 fp16
#define SMEM_DYN (SMEMA + 2 * SMEMB)

__device__ float    g_xx[NN];
__device__ float    g_s2[NN];
__device__ float    g_ee[KK];
__device__ unsigned g_emaxb;
__device__ int      g_cnt[KK];
__device__ double   g_sq;
__device__ unsigned g_XH[(size_t)NN * 128];  // fp16(2x) pairs
__device__ unsigned g_EH[(size_t)KK * 128];  // fp16(1024*e) pairs
__device__ unsigned long long g_cand[(size_t)NN * CAP];  // (d~ bits << 32) | k
__device__ float    g_rminf[NN];             // final approx row min
__device__ int      g_ccnt[NN];

// ---- helpers ----
__device__ __forceinline__ uint32_t smem_u32(const void* p) {
    uint32_t a;
    asm("{ .reg .u64 t; cvta.to.shared.u64 t, %1; cvt.u32.u64 %0, t; }" : "=r"(a) : "l"(p));
    return a;
}
__device__ __forceinline__ void cp16(uint32_t dst, const void* src) {
    uint64_t gs;
    asm("cvta.to.global.u64 %0, %1;" : "=l"(gs) : "l"(src));
    asm volatile("cp.async.cg.shared.global [%0], [%1], 16;" :: "r"(dst), "l"(gs));
}
#define CP_COMMIT() asm volatile("cp.async.commit_group;" ::: "memory")
#define CP_WAIT0()  asm volatile("cp.async.wait_group 0;" ::: "memory")
__device__ __forceinline__ void ldsm4(uint32_t a, uint32_t& r0, uint32_t& r1,
                                      uint32_t& r2, uint32_t& r3) {
    asm volatile("ldmatrix.sync.aligned.m8n8.x4.shared.b16 {%0,%1,%2,%3}, [%4];"
                 : "=r"(r0), "=r"(r1), "=r"(r2), "=r"(r3) : "r"(a));
}
__device__ __forceinline__ void mma16(float* c, const uint32_t* a, uint32_t b0, uint32_t b1) {
    asm volatile("mma.sync.aligned.m16n8k16.row.col.f32.f16.f16.f32 "
                 "{%0,%1,%2,%3}, {%4,%5,%6,%7}, {%8,%9}, {%0,%1,%2,%3};"
                 : "+f"(c[0]), "+f"(c[1]), "+f"(c[2]), "+f"(c[3])
                 : "r"(a[0]), "r"(a[1]), "r"(a[2]), "r"(a[3]), "r"(b0), "r"(b1));
}
__device__ __forceinline__ unsigned packh2(float a, float b) {
    unsigned lo = __half_as_ushort(__float2half_rn(a));
    unsigned hi = __half_as_ushort(__float2half_rn(b));
    return lo | (hi << 16);
}

// ---- init ----
__global__ void k_init() {
    int i = blockIdx.x * blockDim.x + threadIdx.x;
    if (i < KK) g_cnt[i] = 0;
    if (i == 0) { g_sq = 0.0; g_emaxb = 0u; }
}

// ---- prep x: exact xx (reference chain), S2, fp16(2x) ----
__global__ void k_prep_x(const float* __restrict__ x) {
    int gw = (blockIdx.x * blockDim.x + threadIdx.x) >> 5, lane = threadIdx.x & 31;
    if (gw >= NN) return;
    const float* p = x + (size_t)gw * DD;
    float s = 0.f, s2 = 0.f;
#pragma unroll
    for (int j = 0; j < 8; j++) {
        float t = p[lane + 32 * j];
        s  = __fadd_rn(s, __fmul_rn(t, t));
        s2 += fabsf(t);
    }
    const float2* p2 = (const float2*)p;
#pragma unroll
    for (int j = 0; j < 4; j++) {
        int id2 = lane + 32 * j;
        float2 v = p2[id2];
        g_XH[(size_t)gw * 128 + id2] = packh2(2.0f * v.x, 2.0f * v.y);
    }
#pragma unroll
    for (int off = 16; off; off >>= 1) {
        s  = __fadd_rn(s, __shfl_xor_sync(0xffffffffu, s, off));
        s2 += __shfl_xor_sync(0xffffffffu, s2, off);
    }
    if (lane == 0) { g_xx[gw] = s; g_s2[gw] = 2.0f * s2; }
}

// ---- prep e: exact ee, global max|e|, fp16(1024*e) ----
__global__ void k_prep_e(const float* __restrict__ emb) {
    int gw = (blockIdx.x * blockDim.x + threadIdx.x) >> 5, lane = threadIdx.x & 31;
    if (gw >= KK) return;
    const float* p = emb + (size_t)gw * DD;
    float s = 0.f, m = 0.f;
#pragma unroll
    for (int j = 0; j < 8; j++) {
        float t = p[lane + 32 * j];
        s = __fadd_rn(s, __fmul_rn(t, t));
        m = fmaxf(m, fabsf(t));
    }
    const float2* p2 = (const float2*)p;
#pragma unroll
    for (int j = 0; j < 4; j++) {
        int id2 = lane + 32 * j;
        float2 v = p2[id2];
        g_EH[(size_t)gw * 128 + id2] = packh2(1024.0f * v.x, 1024.0f * v.y);
    }
#pragma unroll
    for (int off = 16; off; off >>= 1) {
        s = __fadd_rn(s, __shfl_xor_sync(0xffffffffu, s, off));
        m = fmaxf(m, __shfl_xor_sync(0xffffffffu, m, off));
    }
    if (lane == 0) { g_ee[gw] = s; atomicMax(&g_emaxb, __float_as_uint(m)); }
}

// ---- B full-tile load: 128 codes x 256 fp16 = 4096 16B units, swizzled ----
__device__ __forceinline__ void bload(uint32_t sB, int t, int tid) {
    const uint32_t base = sB + (t & 1) * SMEMB;
    const unsigned* src = &g_EH[(size_t)(t * 128) * 128];
#pragma unroll
    for (int i = 0; i < 8; i++) {
        int idx = i * 512 + tid;
        int sc = idx >> 10, n = (idx >> 3) & 127, u = idx & 7;
        cp16(base + sc * 16384 + n * 128 + ((u ^ (n & 7)) << 4),
             src + (size_t)n * 128 + sc * 32 + u * 4);
    }
}

// ---- fragment bundle: one k16 stage of A(32 rows) + B(32 cols) ----
struct Frag { uint32_t a0[4], a1[4], b[2][4]; };

__device__ __forceinline__ void ldstage(Frag& f, uint32_t sA, uint32_t bBuf,
                                        int s, int rA0, int uqA, int nB0, int uqB) {
    const uint32_t aCh = sA + (s >> 2) * 16384;
    const uint32_t bSc = bBuf + (s >> 2) * 16384;
    const int us = (s & 3) * 2;
    {
        int u = us + uqA;
        ldsm4(aCh + rA0 * 128 + ((u ^ (rA0 & 7)) << 4), f.a0[0], f.a0[1], f.a0[2], f.a0[3]);
        int r1 = rA0 + 16;
        ldsm4(aCh + r1 * 128 + ((u ^ (r1 & 7)) << 4), f.a1[0], f.a1[1], f.a1[2], f.a1[3]);
    }
#pragma unroll
    for (int jp = 0; jp < 2; jp++) {
        int n = nB0 + jp * 16;
        int u = us + uqB;
        ldsm4(bSc + n * 128 + ((u ^ (n & 7)) << 4),
              f.b[jp][0], f.b[jp][1], f.b[jp][2], f.b[jp][3]);
    }
}

// ---- fp16 mma GEMM + epsilon filter (512 threads, warp tile 32x32) ----
__global__ __launch_bounds__(512, 1) void k_mma() {
    extern __shared__ __align__(128) char dsm[];
    __shared__ float    ees[2][128];
    __shared__ unsigned rmin[128];
    __shared__ int      scnt[128];

    const int tid = threadIdx.x, lane = tid & 31, wid = tid >> 5;
    const int wm = wid & 3, wn = wid >> 2;       // 4x4 warp grid
    const int row0 = blockIdx.x * 128;
    const uint32_t sA = smem_u32(dsm);
    const uint32_t sB = sA + SMEMA;
    const float emax = __uint_as_float(g_emaxb);

    if (tid < 128) {
        rmin[tid] = 0x7F7FFFFFu;
        scnt[tid] = 0;
        ees[0][tid] = g_ee[tid];    // tile 0 ees, published by barrier below
    }

    // A resident: 4096 16B units, 4 sub-chunks of (128 rows x 64 fp16)
#pragma unroll
    for (int i = 0; i < 8; i++) {
        int idx = tid + i * 512;
        int sc = idx >> 10, r = (idx >> 3) & 127, u = idx & 7;
        cp16(sA + sc * 16384 + r * 128 + ((u ^ (r & 7)) << 4),
             &g_XH[(size_t)(row0 + r) * 128 + sc * 32 + u * 4]);
    }
    bload(sB, 0, tid);
    CP_COMMIT();

    // ldmatrix lane constants
    const int lrow = lane & 7, q = lane >> 3;
    const int rA0 = wm * 32 + ((q & 1) << 3) + lrow;
    const int uqA = q >> 1;
    const int nB0 = wn * 32 + ((q >> 1) << 3) + lrow;
    const int uqB = q & 1;
    const int rbase = wm * 32 + (lane >> 2);
    const int colb  = wn * 32 + ((lane & 3) << 1);
    float xr[4], epsr[4];
#pragma unroll
    for (int s = 0; s < 4; s++) {
        xr[s]   = g_xx[row0 + rbase + s * 8];
        epsr[s] = EPSC * g_s2[row0 + rbase + s * 8] * emax + EPSA;
    }

    float acc[2][4][4];
#pragma unroll
    for (int i = 0; i < 2; i++)
#pragma unroll
        for (int j = 0; j < 4; j++)
#pragma unroll
            for (int p = 0; p < 4; p++) acc[i][j][p] = 0.f;

    Frag fr[2];

#pragma unroll 1
    for (int t = 0; t < 32; t++) {
        // one barrier per tile: publishes B tile t + ees[t&1], retires buffer (t+1)&1
        CP_WAIT0();
        __syncthreads();
        if (t + 1 < 32) {
            bload(sB, t + 1, tid);
            CP_COMMIT();
            if (tid < 128) ees[(t + 1) & 1][tid] = g_ee[(t + 1) * 128 + tid];
        }
        const uint32_t bBuf = sB + (t & 1) * SMEMB;
        const float* eev = ees[t & 1];

        // 16 k16 stages, fragment double-buffered
        ldstage(fr[0], sA, bBuf, 0, rA0, uqA, nB0, uqB);
#pragma unroll
        for (int s = 0; s < 16; s++) {
            if (s < 15)
                ldstage(fr[(s + 1) & 1], sA, bBuf, s + 1, rA0, uqA, nB0, uqB);
            Frag& f = fr[s & 1];
#pragma unroll
            for (int jp = 0; jp < 2; jp++) {
                mma16(acc[0][jp * 2],     f.a0, f.b[jp][0], f.b[jp][1]);
                mma16(acc[0][jp * 2 + 1], f.a0, f.b[jp][2], f.b[jp][3]);
                mma16(acc[1][jp * 2],     f.a1, f.b[jp][0], f.b[jp][1]);
                mma16(acc[1][jp * 2 + 1], f.a1, f.b[jp][2], f.b[jp][3]);
            }
        }

        // ---- barrier-free tile epilogue (acc scaled by 1024: undo exactly) ----
        {
            float lm[4] = {3.4e38f, 3.4e38f, 3.4e38f, 3.4e38f};
#pragma unroll
            for (int i = 0; i < 2; i++)
#pragma unroll
                for (int j = 0; j < 4; j++)
#pragma unroll
                    for (int p = 0; p < 4; p++) {
                        int slot = i * 2 + (p >> 1);
                        float dd = (xr[slot] + eev[colb + j * 8 + (p & 1)])
                                   - acc[i][j][p] * INV1024;
                        lm[slot] = fminf(lm[slot], dd);
                    }
#pragma unroll
            for (int s = 0; s < 4; s++) {
                lm[s] = fminf(lm[s], __shfl_xor_sync(0xffffffffu, lm[s], 1));
                lm[s] = fminf(lm[s], __shfl_xor_sync(0xffffffffu, lm[s], 2));
            }
            float thr[4];
#pragma unroll
            for (int s = 0; s < 4; s++) {
                atomicMin(&rmin[rbase + s * 8], __float_as_uint(lm[s]));
                // unsynced read: any subset-min + eps is a valid threshold
                thr[s] = __uint_as_float(rmin[rbase + s * 8]) + epsr[s];
            }
#pragma unroll
            for (int i = 0; i < 2; i++)
#pragma unroll
                for (int j = 0; j < 4; j++)
#pragma unroll
                    for (int p = 0; p < 4; p++) {
                        int slot = i * 2 + (p >> 1);
                        float dd = (xr[slot] + eev[colb + j * 8 + (p & 1)])
                                   - acc[i][j][p] * INV1024;
                        if (dd < thr[slot]) {
                            int rl = rbase + slot * 8;
                            int pos = atomicAdd(&scnt[rl], 1);
                            if (pos < CAP)
                                g_cand[(size_t)(row0 + rl) * CAP + pos] =
                                    (((unsigned long long)__float_as_uint(dd)) << 32)
                                    | (unsigned)(t * 128 + colb + j * 8 + (p & 1));
                        }
                        acc[i][j][p] = 0.f;
                    }
        }
    }
    __syncthreads();
    if (tid < 128) {
        g_ccnt[row0 + tid]  = scnt[tid];
        g_rminf[row0 + tid] = __uint_as_float(rmin[tid]);   // final row min
    }
}

// ---- fused: pruned exact rescore + gather + ST output + MSE + histogram ----
__global__ void k_finish(const float* __restrict__ x, const float* __restrict__ emb,
                         const float* __restrict__ mask, float* __restrict__ out) {
    __shared__ double sh[8];
    const int lane = threadIdx.x & 31, w = threadIdx.x >> 5;
    const int gw = blockIdx.x * 8 + w;

    // --- pruned exact rescore (bit-exact reference chain on survivors) ---
    int cnt = g_ccnt[gw];
    float xr = g_xx[gw];
    // prune threshold vs FINAL row min: survivors ~1-2 per row; argmin guaranteed in
    const float thr = g_rminf[gw]
        + EPSC * g_s2[gw] * __uint_as_float(g_emaxb) + EPSA;
    const float4* x4p = (const float4*)(x + (size_t)gw * DD);
    unsigned long long best = ~0ull;
    if (cnt <= CAP) {
        for (int ci = lane; ci < cnt; ci += 32) {
            unsigned long long pc = g_cand[(size_t)gw * CAP + ci];
            if (__uint_as_float((unsigned)(pc >> 32)) >= thr) continue;  // stale record
            int k = (int)(pc & 0xffffffffull);
            const float4* e4p = (const float4*)(emb + (size_t)k * DD);
            float acc = 0.f;
#pragma unroll 4
            for (int i = 0; i < 64; i++) {          // exact ascending chain, float4 loads
                float4 xv = x4p[i], ev = e4p[i];
                acc = __fmaf_rn(2.0f * xv.x, ev.x, acc);
                acc = __fmaf_rn(2.0f * xv.y, ev.y, acc);
                acc = __fmaf_rn(2.0f * xv.z, ev.z, acc);
                acc = __fmaf_rn(2.0f * xv.w, ev.w, acc);
            }
            float dd = __fadd_rn(__fadd_rn(xr, g_ee[k]), -acc);
            unsigned long long pk =
                (((unsigned long long)__float_as_uint(dd)) << 32) | (unsigned)k;
            if (pk < best) best = pk;
        }
    } else {                                       // overflow: exact full scan
        for (int k = lane; k < KK; k += 32) {
            const float4* e4p = (const float4*)(emb + (size_t)k * DD);
            float acc = 0.f;
            for (int i = 0; i < 64; i++) {
                float4 xv = x4p[i], ev = e4p[i];
                acc = __fmaf_rn(2.0f * xv.x, ev.x, acc);
                acc = __fmaf_rn(2.0f * xv.y, ev.y, acc);
                acc = __fmaf_rn(2.0f * xv.z, ev.z, acc);
                acc = __fmaf_rn(2.0f * xv.w, ev.w, acc);
            }
            float dd = __fadd_rn(__fadd_rn(xr, g_ee[k]), -acc);
            unsigned long long pk =
                (((unsigned long long)__float_as_uint(dd)) << 32) | (unsigned)k;
            if (pk < best) best = pk;
        }
    }
#pragma unroll
    for (int off = 16; off; off >>= 1) {
        unsigned long long o = __shfl_xor_sync(0xffffffffu, best, off);
        if (o < best) best = o;
    }
    const int c = (int)(best & 0xffffffffull);     // all lanes hold the min
    if (lane == 0) {
        atomicAdd(&g_cnt[c], 1);
        out[OUT_IDX_BASE + gw] = (float)c;
    }

    // --- gather + straight-through output + MSE (identical rounding) ---
    const float m = mask[gw];
    const float4* e4p = (const float4*)(emb + (size_t)c * DD);
    float4* o4p = (float4*)(out + (size_t)gw * DD);
    double local = 0.0;
#pragma unroll
    for (int j = 0; j < 2; j++) {
        int i4 = lane + 32 * j;
        float4 e4 = e4p[i4], x4 = x4p[i4], o4;
        float qv, d1;
        qv = __fmul_rn(e4.x, m); d1 = __fadd_rn(qv, -x4.x); o4.x = __fadd_rn(x4.x, d1);
        local += (double)__fmul_rn(d1, d1);
        qv = __fmul_rn(e4.y, m); d1 = __fadd_rn(qv, -x4.y); o4.y = __fadd_rn(x4.y, d1);
        local += (double)__fmul_rn(d1, d1);
        qv = __fmul_rn(e4.z, m); d1 = __fadd_rn(qv, -x4.z); o4.z = __fadd_rn(x4.z, d1);
        local += (double)__fmul_rn(d1, d1);
        qv = __fmul_rn(e4.w, m); d1 = __fadd_rn(qv, -x4.w); o4.w = __fadd_rn(x4.w, d1);
        local += (double)__fmul_rn(d1, d1);
        o4p[i4] = o4;
    }
#pragma unroll
    for (int off = 16; off; off >>= 1) local += __shfl_xor_sync(0xffffffffu, local, off);
    if (lane == 0) sh[w] = local;
    __syncthreads();
    if (threadIdx.x == 0) {
        double s = 0.0;
        for (int i = 0; i < 8; i++) s += sh[i];
        atomicAdd(&g_sq, s);
    }
}

__global__ void k_final(float* __restrict__ out) {
    __shared__ double sh[8];
    double local = 0.0;
    for (int k = threadIdx.x; k < KK; k += blockDim.x) {
        float p = __fmul_rn((float)g_cnt[k], 1.0f / 32768.0f);
        local += (double)__fmul_rn(p, logf(__fadd_rn(p, 1e-8f)));
    }
#pragma unroll
    for (int off = 16; off; off >>= 1) local += __shfl_xor_sync(0xffffffffu, local, off);
    int lane = threadIdx.x & 31, w = threadIdx.x >> 5;
    if (lane == 0) sh[w] = local;
    __syncthreads();
    if (threadIdx.x == 0) {
        double H = 0.0;
        for (int i = 0; i < (int)(blockDim.x >> 5); i++) H += sh[i];
        double mse = g_sq / (double)(NN * DD);
        float ql = (float)mse;
        out[OUT_SCALAR_BASE + 0] = __fmul_rn(0.25f, ql);
        out[OUT_SCALAR_BASE + 1] = ql;
        out[OUT_SCALAR_BASE + 2] = expf(-(float)H);
    }
}

extern "C" void kernel_launch(void* const* d_in, const int* in_sizes, int n_in,
                              void* d_out, int out_size) {
    const float* x    = (const float*)d_in[0];
    const float* emb  = (const float*)d_in[1];
    const float* mask = (const float*)d_in[2];
    float* out = (float*)d_out;

    cudaFuncSetAttribute(k_mma, cudaFuncAttributeMaxDynamicSharedMemorySize, SMEM_DYN);

    k_init<<<16, 256>>>();
    k_prep_x<<<(NN * 32) / 256, 256>>>(x);
    k_prep_e<<<(KK * 32) / 256, 256>>>(emb);
    k_mma<<<NN / 128, 512, SMEM_DYN>>>();
    k_finish<<<NN / 8, 256>>>(x, emb, mask, out);
    k_final<<<1, 256>>>(out);
}

// round 15
// speedup vs baseline: 2.1707x; 1.0192x over previous
#include <cuda_runtime.h>
#include <cuda_fp16.h>
#include <math.h>
#include <stdint.h>

#define NN 32768
#define DD 256
#define KK 4096
#define OUT_SCALAR_BASE (NN * DD)
#define OUT_IDX_BASE    (NN * DD + 3)
#define CAP 28
#define EPSC 0.00390625f      // 2^-8: 4x margin over rigorous 2^-10 fp16 bound
#define EPSA 1.5e-4f          // covers 2*ulp(256) + fp32 accum chain
#define INV1024 9.765625e-4f  // exact 2^-10 (undo e prescale)
#define SMEMA 65536           // A resident: 4 sub-chunks * 128 rows * 64 fp16
#define SMEMB 65536           // one B chunk: 256 codes * 128 dims fp16
#define SMEM_DYN (SMEMA + 2 * SMEMB)

__device__ float    g_xx[NN];
__device__ float    g_s2[NN];
__device__ float    g_ee[KK];
__device__ unsigned g_emaxb;
__device__ int      g_cnt[KK];
__device__ double   g_sq;
__device__ unsigned g_XH[(size_t)NN * 128];  // fp16(2x) pairs
__device__ unsigned g_EH[(size_t)KK * 128];  // fp16(1024*e) pairs
__device__ unsigned long long g_cand[(size_t)NN * CAP];  // (d~ bits << 32) | k
__device__ float    g_rminf[NN];             // final approx row min
__device__ int      g_ccnt[NN];

// ---- helpers ----
__device__ __forceinline__ uint32_t smem_u32(const void* p) {
    uint32_t a;
    asm("{ .reg .u64 t; cvta.to.shared.u64 t, %1; cvt.u32.u64 %0, t; }" : "=r"(a) : "l"(p));
    return a;
}
__device__ __forceinline__ void cp16(uint32_t dst, const void* src) {
    uint64_t gs;
    asm("cvta.to.global.u64 %0, %1;" : "=l"(gs) : "l"(src));
    asm volatile("cp.async.cg.shared.global [%0], [%1], 16;" :: "r"(dst), "l"(gs));
}
#define CP_COMMIT() asm volatile("cp.async.commit_group;" ::: "memory")
#define CP_WAIT0()  asm volatile("cp.async.wait_group 0;" ::: "memory")
__device__ __forceinline__ void ldsm4(uint32_t a, uint32_t& r0, uint32_t& r1,
                                      uint32_t& r2, uint32_t& r3) {
    asm volatile("ldmatrix.sync.aligned.m8n8.x4.shared.b16 {%0,%1,%2,%3}, [%4];"
                 : "=r"(r0), "=r"(r1), "=r"(r2), "=r"(r3) : "r"(a));
}
__device__ __forceinline__ void mma16(float* c, const uint32_t* a, uint32_t b0, uint32_t b1) {
    asm volatile("mma.sync.aligned.m16n8k16.row.col.f32.f16.f16.f32 "
                 "{%0,%1,%2,%3}, {%4,%5,%6,%7}, {%8,%9}, {%0,%1,%2,%3};"
                 : "+f"(c[0]), "+f"(c[1]), "+f"(c[2]), "+f"(c[3])
                 : "r"(a[0]), "r"(a[1]), "r"(a[2]), "r"(a[3]), "r"(b0), "r"(b1));
}
__device__ __forceinline__ unsigned packh2(float a, float b) {
    unsigned lo = __half_as_ushort(__float2half_rn(a));
    unsigned hi = __half_as_ushort(__float2half_rn(b));
    return lo | (hi << 16);
}

// ---- init ----
__global__ void k_init() {
    int i = blockIdx.x * blockDim.x + threadIdx.x;
    if (i < KK) g_cnt[i] = 0;
    if (i == 0) { g_sq = 0.0; g_emaxb = 0u; }
}

// ---- prep x: exact xx (reference chain), S2, fp16(2x) ----
__global__ void k_prep_x(const float* __restrict__ x) {
    int gw = (blockIdx.x * blockDim.x + threadIdx.x) >> 5, lane = threadIdx.x & 31;
    if (gw >= NN) return;
    const float* p = x + (size_t)gw * DD;
    float s = 0.f, s2 = 0.f;
#pragma unroll
    for (int j = 0; j < 8; j++) {
        float t = p[lane + 32 * j];
        s  = __fadd_rn(s, __fmul_rn(t, t));
        s2 += fabsf(t);
    }
    const float2* p2 = (const float2*)p;
#pragma unroll
    for (int j = 0; j < 4; j++) {
        int id2 = lane + 32 * j;
        float2 v = p2[id2];
        g_XH[(size_t)gw * 128 + id2] = packh2(2.0f * v.x, 2.0f * v.y);
    }
#pragma unroll
    for (int off = 16; off; off >>= 1) {
        s  = __fadd_rn(s, __shfl_xor_sync(0xffffffffu, s, off));
        s2 += __shfl_xor_sync(0xffffffffu, s2, off);
    }
    if (lane == 0) { g_xx[gw] = s; g_s2[gw] = 2.0f * s2; }
}

// ---- prep e: exact ee, global max|e|, fp16(1024*e) ----
__global__ void k_prep_e(const float* __restrict__ emb) {
    int gw = (blockIdx.x * blockDim.x + threadIdx.x) >> 5, lane = threadIdx.x & 31;
    if (gw >= KK) return;
    const float* p = emb + (size_t)gw * DD;
    float s = 0.f, m = 0.f;
#pragma unroll
    for (int j = 0; j < 8; j++) {
        float t = p[lane + 32 * j];
        s = __fadd_rn(s, __fmul_rn(t, t));
        m = fmaxf(m, fabsf(t));
    }
    const float2* p2 = (const float2*)p;
#pragma unroll
    for (int j = 0; j < 4; j++) {
        int id2 = lane + 32 * j;
        float2 v = p2[id2];
        g_EH[(size_t)gw * 128 + id2] = packh2(1024.0f * v.x, 1024.0f * v.y);
    }
#pragma unroll
    for (int off = 16; off; off >>= 1) {
        s = __fadd_rn(s, __shfl_xor_sync(0xffffffffu, s, off));
        m = fmaxf(m, __shfl_xor_sync(0xffffffffu, m, off));
    }
    if (lane == 0) { g_ee[gw] = s; atomicMax(&g_emaxb, __float_as_uint(m)); }
}

// ---- B chunk load: tile t=(g>>1), half c=(g&1); 256 codes x 128 dims ----
// chunk = 2 sub-chunks of (256 codes x 64 dims), 32KB each, swizzled rows of 128B
__device__ __forceinline__ void bload(uint32_t sB, int g, int tid) {
    const int t = g >> 1, c = g & 1;
    const uint32_t base = sB + (g & 1) * SMEMB;
    const unsigned* src = g_EH + (size_t)(t * 256) * 128 + c * 64;
#pragma unroll
    for (int i = 0; i < 8; i++) {
        int idx = i * 512 + tid;
        int s2 = idx >> 11, n = (idx >> 3) & 255, u = idx & 7;
        cp16(base + s2 * 32768 + n * 128 + ((u ^ (n & 7)) << 4),
             src + (size_t)n * 128 + s2 * 32 + u * 4);
    }
}

// ---- fp16 mma GEMM + epsilon filter (512 threads, warp tile 32x64, CTA 128x256) ----
__global__ __launch_bounds__(512, 1) void k_mma() {
    extern __shared__ __align__(128) char dsm[];
    __shared__ float    ees[2][256];
    __shared__ unsigned rmin[128];
    __shared__ int      scnt[128];

    const int tid = threadIdx.x, lane = tid & 31, wid = tid >> 5;
    const int wm = wid & 3, wn = wid >> 2;       // 4 row groups x 4 col groups of 64
    const int row0 = blockIdx.x * 128;
    const uint32_t sA = smem_u32(dsm);
    const uint32_t sB = sA + SMEMA;
    const float emax = __uint_as_float(g_emaxb);

    if (tid < 128) { rmin[tid] = 0x7F7FFFFFu; scnt[tid] = 0; }

    // A resident: 4096 16B units, 4 sub-chunks of (128 rows x 64 fp16)
#pragma unroll
    for (int i = 0; i < 8; i++) {
        int idx = tid + i * 512;
        int sc = idx >> 10, r = (idx >> 3) & 127, u = idx & 7;
        cp16(sA + sc * 16384 + r * 128 + ((u ^ (r & 7)) << 4),
             &g_XH[(size_t)(row0 + r) * 128 + sc * 32 + u * 4]);
    }
    bload(sB, 0, tid);
    CP_COMMIT();

    // ldmatrix lane constants
    const int lrow = lane & 7, q = lane >> 3;
    const int rA0 = wm * 32 + ((q & 1) << 3) + lrow;
    const int uqA = q >> 1;
    const int nB0 = wn * 64 + ((q >> 1) << 3) + lrow;
    const int uqB = q & 1;
    const int rbase = wm * 32 + (lane >> 2);
    const int colb  = wn * 64 + ((lane & 3) << 1);
    float xr[4], epsr[4];
#pragma unroll
    for (int s = 0; s < 4; s++) {
        xr[s]   = g_xx[row0 + rbase + s * 8];
        epsr[s] = EPSC * g_s2[row0 + rbase + s * 8] * emax + EPSA;
    }

    float acc[2][8][4];
#pragma unroll
    for (int i = 0; i < 2; i++)
#pragma unroll
        for (int j = 0; j < 8; j++)
#pragma unroll
            for (int p = 0; p < 4; p++) acc[i][j][p] = 0.f;

#pragma unroll 1
    for (int t = 0; t < 16; t++) {
#pragma unroll
        for (int c = 0; c < 2; c++) {
            const int g = t * 2 + c;
            // 1 barrier per chunk: publishes chunk g AND retires buffer g-1
            CP_WAIT0();
            __syncthreads();
            if (g + 1 < 32) { bload(sB, g + 1, tid); CP_COMMIT(); }
            if (c == 0 && tid < 256) ees[t & 1][tid] = g_ee[t * 256 + tid];

            const uint32_t bBuf = sB + (g & 1) * SMEMB;
            // 8 k16 stages; ksub = c*2 + (s>>2): ascending k order preserved
#pragma unroll
            for (int s = 0; s < 8; s++) {
                const uint32_t aCh = sA + (c * 2 + (s >> 2)) * 16384;
                const uint32_t bSc = bBuf + (s >> 2) * 32768;
                const int us = (s & 3) * 2;
                uint32_t a0[4], a1[4];
                {
                    int u = us + uqA;
                    ldsm4(aCh + rA0 * 128 + ((u ^ (rA0 & 7)) << 4),
                          a0[0], a0[1], a0[2], a0[3]);
                    int r1 = rA0 + 16;
                    ldsm4(aCh + r1 * 128 + ((u ^ (r1 & 7)) << 4),
                          a1[0], a1[1], a1[2], a1[3]);
                }
                uint32_t b[4][4];
#pragma unroll
                for (int jp = 0; jp < 4; jp++) {
                    int n = nB0 + jp * 16;
                    int u = us + uqB;
                    ldsm4(bSc + n * 128 + ((u ^ (n & 7)) << 4),
                          b[jp][0], b[jp][1], b[jp][2], b[jp][3]);
                }
#pragma unroll
                for (int jp = 0; jp < 4; jp++) {
                    mma16(acc[0][jp * 2],     a0, b[jp][0], b[jp][1]);
                    mma16(acc[0][jp * 2 + 1], a0, b[jp][2], b[jp][3]);
                    mma16(acc[1][jp * 2],     a1, b[jp][0], b[jp][1]);
                    mma16(acc[1][jp * 2 + 1], a1, b[jp][2], b[jp][3]);
                }
            }
        }

        // ---- barrier-free tile epilogue (acc scaled by 1024: undo exactly) ----
        {
            const float* eev = ees[t & 1];
            float lm[4] = {3.4e38f, 3.4e38f, 3.4e38f, 3.4e38f};
#pragma unroll
            for (int i = 0; i < 2; i++)
#pragma unroll
                for (int j = 0; j < 8; j++)
#pragma unroll
                    for (int p = 0; p < 4; p++) {
                        int slot = i * 2 + (p >> 1);
                        float dd = (xr[slot] + eev[colb + j * 8 + (p & 1)])
                                   - acc[i][j][p] * INV1024;
                        lm[slot] = fminf(lm[slot], dd);
                    }
#pragma unroll
            for (int s = 0; s < 4; s++) {
                lm[s] = fminf(lm[s], __shfl_xor_sync(0xffffffffu, lm[s], 1));
                lm[s] = fminf(lm[s], __shfl_xor_sync(0xffffffffu, lm[s], 2));
            }
            float thr[4];
#pragma unroll
            for (int s = 0; s < 4; s++) {
                atomicMin(&rmin[rbase + s * 8], __float_as_uint(lm[s]));
                // unsynced read: any subset-min + eps is a valid threshold
                thr[s] = __uint_as_float(rmin[rbase + s * 8]) + epsr[s];
            }
#pragma unroll
            for (int i = 0; i < 2; i++)
#pragma unroll
                for (int j = 0; j < 8; j++)
#pragma unroll
                    for (int p = 0; p < 4; p++) {
                        int slot = i * 2 + (p >> 1);
                        float dd = (xr[slot] + eev[colb + j * 8 + (p & 1)])
                                   - acc[i][j][p] * INV1024;
                        if (dd < thr[slot]) {
                            int rl = rbase + slot * 8;
                            int pos = atomicAdd(&scnt[rl], 1);
                            if (pos < CAP)
                                g_cand[(size_t)(row0 + rl) * CAP + pos] =
                                    (((unsigned long long)__float_as_uint(dd)) << 32)
                                    | (unsigned)(t * 256 + colb + j * 8 + (p & 1));
                        }
                        acc[i][j][p] = 0.f;
                    }
        }
    }
    __syncthreads();
    if (tid < 128) {
        g_ccnt[row0 + tid]  = scnt[tid];
        g_rminf[row0 + tid] = __uint_as_float(rmin[tid]);   // final row min
    }
}

// ---- fused: pruned exact rescore + gather + ST output + MSE + histogram ----
__global__ void k_finish(const float* __restrict__ x, const float* __restrict__ emb,
                         const float* __restrict__ mask, float* __restrict__ out) {
    __shared__ double sh[8];
    const int lane = threadIdx.x & 31, w = threadIdx.x >> 5;
    const int gw = blockIdx.x * 8 + w;

    // --- pruned exact rescore (bit-exact reference chain on survivors) ---
    int cnt = g_ccnt[gw];
    float xr = g_xx[gw];
    // prune threshold vs FINAL row min: survivors ~1-2 per row; argmin guaranteed in
    const float thr = g_rminf[gw]
        + EPSC * g_s2[gw] * __uint_as_float(g_emaxb) + EPSA;
    const float4* x4p = (const float4*)(x + (size_t)gw * DD);
    unsigned long long best = ~0ull;
    if (cnt <= CAP) {
        for (int ci = lane; ci < cnt; ci += 32) {
            unsigned long long pc = g_cand[(size_t)gw * CAP + ci];
            if (__uint_as_float((unsigned)(pc >> 32)) >= thr) continue;  // stale record
            int k = (int)(pc & 0xffffffffull);
            const float4* e4p = (const float4*)(emb + (size_t)k * DD);
            float acc = 0.f;
#pragma unroll 4
            for (int i = 0; i < 64; i++) {          // exact ascending chain, float4 loads
                float4 xv = x4p[i], ev = e4p[i];
                acc = __fmaf_rn(2.0f * xv.x, ev.x, acc);
                acc = __fmaf_rn(2.0f * xv.y, ev.y, acc);
                acc = __fmaf_rn(2.0f * xv.z, ev.z, acc);
                acc = __fmaf_rn(2.0f * xv.w, ev.w, acc);
            }
            float dd = __fadd_rn(__fadd_rn(xr, g_ee[k]), -acc);
            unsigned long long pk =
                (((unsigned long long)__float_as_uint(dd)) << 32) | (unsigned)k;
            if (pk < best) best = pk;
        }
    } else {                                       // overflow: exact full scan
        for (int k = lane; k < KK; k += 32) {
            const float4* e4p = (const float4*)(emb + (size_t)k * DD);
            float acc = 0.f;
            for (int i = 0; i < 64; i++) {
                float4 xv = x4p[i], ev = e4p[i];
                acc = __fmaf_rn(2.0f * xv.x, ev.x, acc);
                acc = __fmaf_rn(2.0f * xv.y, ev.y, acc);
                acc = __fmaf_rn(2.0f * xv.z, ev.z, acc);
                acc = __fmaf_rn(2.0f * xv.w, ev.w, acc);
            }
            float dd = __fadd_rn(__fadd_rn(xr, g_ee[k]), -acc);
            unsigned long long pk =
                (((unsigned long long)__float_as_uint(dd)) << 32) | (unsigned)k;
            if (pk < best) best = pk;
        }
    }
#pragma unroll
    for (int off = 16; off; off >>= 1) {
        unsigned long long o = __shfl_xor_sync(0xffffffffu, best, off);
        if (o < best) best = o;
    }
    const int c = (int)(best & 0xffffffffull);     // all lanes hold the min
    if (lane == 0) {
        atomicAdd(&g_cnt[c], 1);
        out[OUT_IDX_BASE + gw] = (float)c;
    }

    // --- gather + straight-through output + MSE (identical rounding) ---
    const float m = mask[gw];
    const float4* e4p = (const float4*)(emb + (size_t)c * DD);
    float4* o4p = (float4*)(out + (size_t)gw * DD);
    double local = 0.0;
#pragma unroll
    for (int j = 0; j < 2; j++) {
        int i4 = lane + 32 * j;
        float4 e4 = e4p[i4], x4 = x4p[i4], o4;
        float qv, d1;
        qv = __fmul_rn(e4.x, m); d1 = __fadd_rn(qv, -x4.x); o4.x = __fadd_rn(x4.x, d1);
        local += (double)__fmul_rn(d1, d1);
        qv = __fmul_rn(e4.y, m); d1 = __fadd_rn(qv, -x4.y); o4.y = __fadd_rn(x4.y, d1);
        local += (double)__fmul_rn(d1, d1);
        qv = __fmul_rn(e4.z, m); d1 = __fadd_rn(qv, -x4.z); o4.z = __fadd_rn(x4.z, d1);
        local += (double)__fmul_rn(d1, d1);
        qv = __fmul_rn(e4.w, m); d1 = __fadd_rn(qv, -x4.w); o4.w = __fadd_rn(x4.w, d1);
        local += (double)__fmul_rn(d1, d1);
        o4p[i4] = o4;
    }
#pragma unroll
    for (int off = 16; off; off >>= 1) local += __shfl_xor_sync(0xffffffffu, local, off);
    if (lane == 0) sh[w] = local;
    __syncthreads();
    if (threadIdx.x == 0) {
        double s = 0.0;
        for (int i = 0; i < 8; i++) s += sh[i];
        atomicAdd(&g_sq, s);
    }
}

__global__ void k_final(float* __restrict__ out) {
    __shared__ double sh[8];
    double local = 0.0;
    for (int k = threadIdx.x; k < KK; k += blockDim.x) {
        float p = __fmul_rn((float)g_cnt[k], 1.0f / 32768.0f);
        local += (double)__fmul_rn(p, logf(__fadd_rn(p, 1e-8f)));
    }
#pragma unroll
    for (int off = 16; off; off >>= 1) local += __shfl_xor_sync(0xffffffffu, local, off);
    int lane = threadIdx.x & 31, w = threadIdx.x >> 5;
    if (lane == 0) sh[w] = local;
    __syncthreads();
    if (threadIdx.x == 0) {
        double H = 0.0;
        for (int i = 0; i < (int)(blockDim.x >> 5); i++) H += sh[i];
        double mse = g_sq / (double)(NN * DD);
        float ql = (float)mse;
        out[OUT_SCALAR_BASE + 0] = __fmul_rn(0.25f, ql);
        out[OUT_SCALAR_BASE + 1] = ql;
        out[OUT_SCALAR_BASE + 2] = expf(-(float)H);
    }
}

extern "C" void kernel_launch(void* const* d_in, const int* in_sizes, int n_in,
                              void* d_out, int out_size) {
    const float* x    = (const float*)d_in[0];
    const float* emb  = (const float*)d_in[1];
    const float* mask = (const float*)d_in[2];
    float* out = (float*)d_out;

    cudaFuncSetAttribute(k_mma, cudaFuncAttributeMaxDynamicSharedMemorySize, SMEM_DYN);

    k_init<<<16, 256>>>();
    k_prep_x<<<(NN * 32) / 256, 256>>>(x);
    k_prep_e<<<(KK * 32) / 256, 256>>>(emb);
    k_mma<<<NN / 128, 512, SMEM_DYN>>>();
    k_finish<<<NN / 8, 256>>>(x, emb, mask, out);
    k_final<<<1, 256>>>(out);
}

// round 16
// speedup vs baseline: 2.3589x; 1.0867x over previous
#include <cuda_runtime.h>
#include <cuda_fp16.h>
#include <math.h>
#include <stdint.h>

#define NN 32768
#define DD 256
#define KK 4096
#define OUT_SCALAR_BASE (NN * DD)
#define OUT_IDX_BASE    (NN * DD + 3)
#define CAP 28
#define EPSC 0.00390625f      // 2^-8: 4x margin over rigorous 2^-10 fp16 bound
#define EPSA 1.5e-4f          // covers 2*ulp(256) + fp32 accum chain
#define INV1024 9.765625e-4f  // exact 2^-10 (undo e prescale)
#define SMEMA 65536           // A resident: 4 sub-chunks * 128 rows * 64 fp16
#define SMEMB 65536           // one B chunk: 256 codes * 128 dims fp16
#define SMEM_DYN (SMEMA + 2 * SMEMB)

__device__ float    g_xx[NN];
__device__ float    g_s2[NN];
__device__ float    g_ee[KK];
__device__ unsigned g_emaxb;                 // never reset: atomicMax idempotent per replay
__device__ int      g_cnt[KK];
__device__ double   g_sq;
__device__ unsigned g_XH[(size_t)NN * 128];  // fp16(2x) pairs
__device__ unsigned g_EH[(size_t)KK * 128];  // fp16(1024*e) pairs
__device__ unsigned long long g_cand[(size_t)NN * CAP];  // (d~ bits << 32) | k
__device__ float    g_rminf[NN];             // final approx row min
__device__ int      g_ccnt[NN];

// ---- helpers ----
__device__ __forceinline__ uint32_t smem_u32(const void* p) {
    uint32_t a;
    asm("{ .reg .u64 t; cvta.to.shared.u64 t, %1; cvt.u32.u64 %0, t; }" : "=r"(a) : "l"(p));
    return a;
}
__device__ __forceinline__ void cp16(uint32_t dst, const void* src) {
    uint64_t gs;
    asm("cvta.to.global.u64 %0, %1;" : "=l"(gs) : "l"(src));
    asm volatile("cp.async.cg.shared.global [%0], [%1], 16;" :: "r"(dst), "l"(gs));
}
#define CP_COMMIT() asm volatile("cp.async.commit_group;" ::: "memory")
#define CP_WAIT0()  asm volatile("cp.async.wait_group 0;" ::: "memory")
__device__ __forceinline__ void ldsm4(uint32_t a, uint32_t& r0, uint32_t& r1,
                                      uint32_t& r2, uint32_t& r3) {
    asm volatile("ldmatrix.sync.aligned.m8n8.x4.shared.b16 {%0,%1,%2,%3}, [%4];"
                 : "=r"(r0), "=r"(r1), "=r"(r2), "=r"(r3) : "r"(a));
}
__device__ __forceinline__ void mma16(float* c, const uint32_t* a, uint32_t b0, uint32_t b1) {
    asm volatile("mma.sync.aligned.m16n8k16.row.col.f32.f16.f16.f32 "
                 "{%0,%1,%2,%3}, {%4,%5,%6,%7}, {%8,%9}, {%0,%1,%2,%3};"
                 : "+f"(c[0]), "+f"(c[1]), "+f"(c[2]), "+f"(c[3])
                 : "r"(a[0]), "r"(a[1]), "r"(a[2]), "r"(a[3]), "r"(b0), "r"(b1));
}
__device__ __forceinline__ unsigned packh2(float a, float b) {
    unsigned lo = __half_as_ushort(__float2half_rn(a));
    unsigned hi = __half_as_ushort(__float2half_rn(b));
    return lo | (hi << 16);
}

// ---- merged prep: x rows (blocks 0..4095), e rows + init (blocks 4096..4607) ----
__global__ void k_prep(const float* __restrict__ x, const float* __restrict__ emb) {
    const int bid = blockIdx.x;
    const int lane = threadIdx.x & 31, w = threadIdx.x >> 5;
    if (bid < 4096) {
        // ---- x row: exact xx (reference chain), S2, fp16(2x) ----
        const int gw = bid * 8 + w;
        const float* p = x + (size_t)gw * DD;
        float s = 0.f, s2 = 0.f;
#pragma unroll
        for (int j = 0; j < 8; j++) {
            float t = p[lane + 32 * j];
            s  = __fadd_rn(s, __fmul_rn(t, t));
            s2 += fabsf(t);
        }
        const float2* p2 = (const float2*)p;
#pragma unroll
        for (int j = 0; j < 4; j++) {
            int id2 = lane + 32 * j;
            float2 v = p2[id2];
            g_XH[(size_t)gw * 128 + id2] = packh2(2.0f * v.x, 2.0f * v.y);
        }
#pragma unroll
        for (int off = 16; off; off >>= 1) {
            s  = __fadd_rn(s, __shfl_xor_sync(0xffffffffu, s, off));
            s2 += __shfl_xor_sync(0xffffffffu, s2, off);
        }
        if (lane == 0) { g_xx[gw] = s; g_s2[gw] = 2.0f * s2; }
    } else {
        const int b2 = bid - 4096;
        // init work (consumed only by later kernels; no intra-kernel ordering needed)
        if (threadIdx.x < 8) g_cnt[b2 * 8 + threadIdx.x] = 0;
        if (b2 == 0 && threadIdx.x == 0) g_sq = 0.0;
        // ---- e row: exact ee, global max|e|, fp16(1024*e) ----
        const int gw = b2 * 8 + w;
        const float* p = emb + (size_t)gw * DD;
        float s = 0.f, m = 0.f;
#pragma unroll
        for (int j = 0; j < 8; j++) {
            float t = p[lane + 32 * j];
            s = __fadd_rn(s, __fmul_rn(t, t));
            m = fmaxf(m, fabsf(t));
        }
        const float2* p2 = (const float2*)p;
#pragma unroll
        for (int j = 0; j < 4; j++) {
            int id2 = lane + 32 * j;
            float2 v = p2[id2];
            g_EH[(size_t)gw * 128 + id2] = packh2(1024.0f * v.x, 1024.0f * v.y);
        }
#pragma unroll
        for (int off = 16; off; off >>= 1) {
            s = __fadd_rn(s, __shfl_xor_sync(0xffffffffu, s, off));
            m = fmaxf(m, __shfl_xor_sync(0xffffffffu, m, off));
        }
        if (lane == 0) { g_ee[gw] = s; atomicMax(&g_emaxb, __float_as_uint(m)); }
    }
}

// ---- B chunk load: tile t=(g>>1), half c=(g&1); 256 codes x 128 dims ----
__device__ __forceinline__ void bload(uint32_t sB, int g, int tid) {
    const int t = g >> 1, c = g & 1;
    const uint32_t base = sB + (g & 1) * SMEMB;
    const unsigned* src = g_EH + (size_t)(t * 256) * 128 + c * 64;
#pragma unroll
    for (int i = 0; i < 8; i++) {
        int idx = i * 512 + tid;
        int s2 = idx >> 11, n = (idx >> 3) & 255, u = idx & 7;
        cp16(base + s2 * 32768 + n * 128 + ((u ^ (n & 7)) << 4),
             src + (size_t)n * 128 + s2 * 32 + u * 4);
    }
}

// ---- fp16 mma GEMM + epsilon filter (512 threads, warp tile 32x64, CTA 128x256) ----
__global__ __launch_bounds__(512, 1) void k_mma() {
    extern __shared__ __align__(128) char dsm[];
    __shared__ float    ees[2][256];
    __shared__ unsigned rmin[128];
    __shared__ int      scnt[128];

    const int tid = threadIdx.x, lane = tid & 31, wid = tid >> 5;
    const int wm = wid & 3, wn = wid >> 2;
    const int row0 = blockIdx.x * 128;
    const uint32_t sA = smem_u32(dsm);
    const uint32_t sB = sA + SMEMA;
    const float emax = __uint_as_float(g_emaxb);

    if (tid < 128) { rmin[tid] = 0x7F7FFFFFu; scnt[tid] = 0; }

#pragma unroll
    for (int i = 0; i < 8; i++) {
        int idx = tid + i * 512;
        int sc = idx >> 10, r = (idx >> 3) & 127, u = idx & 7;
        cp16(sA + sc * 16384 + r * 128 + ((u ^ (r & 7)) << 4),
             &g_XH[(size_t)(row0 + r) * 128 + sc * 32 + u * 4]);
    }
    bload(sB, 0, tid);
    CP_COMMIT();

    const int lrow = lane & 7, q = lane >> 3;
    const int rA0 = wm * 32 + ((q & 1) << 3) + lrow;
    const int uqA = q >> 1;
    const int nB0 = wn * 64 + ((q >> 1) << 3) + lrow;
    const int uqB = q & 1;
    const int rbase = wm * 32 + (lane >> 2);
    const int colb  = wn * 64 + ((lane & 3) << 1);
    float xr[4], epsr[4];
#pragma unroll
    for (int s = 0; s < 4; s++) {
        xr[s]   = g_xx[row0 + rbase + s * 8];
        epsr[s] = EPSC * g_s2[row0 + rbase + s * 8] * emax + EPSA;
    }

    float acc[2][8][4];
#pragma unroll
    for (int i = 0; i < 2; i++)
#pragma unroll
        for (int j = 0; j < 8; j++)
#pragma unroll
            for (int p = 0; p < 4; p++) acc[i][j][p] = 0.f;

#pragma unroll 1
    for (int t = 0; t < 16; t++) {
#pragma unroll
        for (int c = 0; c < 2; c++) {
            const int g = t * 2 + c;
            CP_WAIT0();
            __syncthreads();
            if (g + 1 < 32) { bload(sB, g + 1, tid); CP_COMMIT(); }
            if (c == 0 && tid < 256) ees[t & 1][tid] = g_ee[t * 256 + tid];

            const uint32_t bBuf = sB + (g & 1) * SMEMB;
#pragma unroll
            for (int s = 0; s < 8; s++) {
                const uint32_t aCh = sA + (c * 2 + (s >> 2)) * 16384;
                const uint32_t bSc = bBuf + (s >> 2) * 32768;
                const int us = (s & 3) * 2;
                uint32_t a0[4], a1[4];
                {
                    int u = us + uqA;
                    ldsm4(aCh + rA0 * 128 + ((u ^ (rA0 & 7)) << 4),
                          a0[0], a0[1], a0[2], a0[3]);
                    int r1 = rA0 + 16;
                    ldsm4(aCh + r1 * 128 + ((u ^ (r1 & 7)) << 4),
                          a1[0], a1[1], a1[2], a1[3]);
                }
                uint32_t b[4][4];
#pragma unroll
                for (int jp = 0; jp < 4; jp++) {
                    int n = nB0 + jp * 16;
                    int u = us + uqB;
                    ldsm4(bSc + n * 128 + ((u ^ (n & 7)) << 4),
                          b[jp][0], b[jp][1], b[jp][2], b[jp][3]);
                }
#pragma unroll
                for (int jp = 0; jp < 4; jp++) {
                    mma16(acc[0][jp * 2],     a0, b[jp][0], b[jp][1]);
                    mma16(acc[0][jp * 2 + 1], a0, b[jp][2], b[jp][3]);
                    mma16(acc[1][jp * 2],     a1, b[jp][0], b[jp][1]);
                    mma16(acc[1][jp * 2 + 1], a1, b[jp][2], b[jp][3]);
                }
            }
        }

        // ---- barrier-free tile epilogue ----
        {
            const float* eev = ees[t & 1];
            float lm[4] = {3.4e38f, 3.4e38f, 3.4e38f, 3.4e38f};
#pragma unroll
            for (int i = 0; i < 2; i++)
#pragma unroll
                for (int j = 0; j < 8; j++)
#pragma unroll
                    for (int p = 0; p < 4; p++) {
                        int slot = i * 2 + (p >> 1);
                        float dd = (xr[slot] + eev[colb + j * 8 + (p & 1)])
                                   - acc[i][j][p] * INV1024;
                        lm[slot] = fminf(lm[slot], dd);
                    }
#pragma unroll
            for (int s = 0; s < 4; s++) {
                lm[s] = fminf(lm[s], __shfl_xor_sync(0xffffffffu, lm[s], 1));
                lm[s] = fminf(lm[s], __shfl_xor_sync(0xffffffffu, lm[s], 2));
            }
            float thr[4];
#pragma unroll
            for (int s = 0; s < 4; s++) {
                atomicMin(&rmin[rbase + s * 8], __float_as_uint(lm[s]));
                thr[s] = __uint_as_float(rmin[rbase + s * 8]) + epsr[s];
            }
#pragma unroll
            for (int i = 0; i < 2; i++)
#pragma unroll
                for (int j = 0; j < 8; j++)
#pragma unroll
                    for (int p = 0; p < 4; p++) {
                        int slot = i * 2 + (p >> 1);
                        float dd = (xr[slot] + eev[colb + j * 8 + (p & 1)])
                                   - acc[i][j][p] * INV1024;
                        if (dd < thr[slot]) {
                            int rl = rbase + slot * 8;
                            int pos = atomicAdd(&scnt[rl], 1);
                            if (pos < CAP)
                                g_cand[(size_t)(row0 + rl) * CAP + pos] =
                                    (((unsigned long long)__float_as_uint(dd)) << 32)
                                    | (unsigned)(t * 256 + colb + j * 8 + (p & 1));
                        }
                        acc[i][j][p] = 0.f;
                    }
        }
    }
    __syncthreads();
    if (tid < 128) {
        g_ccnt[row0 + tid]  = scnt[tid];
        g_rminf[row0 + tid] = __uint_as_float(rmin[tid]);
    }
}

// ---- fused: pruned exact rescore (1-survivor fast path) + gather + MSE + hist ----
__global__ void k_finish(const float* __restrict__ x, const float* __restrict__ emb,
                         const float* __restrict__ mask, float* __restrict__ out) {
    __shared__ double sh[8];
    const int lane = threadIdx.x & 31, w = threadIdx.x >> 5;
    const int gw = blockIdx.x * 8 + w;

    int cnt = g_ccnt[gw];
    float xr = g_xx[gw];
    const float thr = g_rminf[gw]
        + EPSC * g_s2[gw] * __uint_as_float(g_emaxb) + EPSA;
    const float4* x4p = (const float4*)(x + (size_t)gw * DD);
    int c;
    if (cnt <= CAP) {
        // cnt <= 28 < 32: each lane owns at most one candidate
        bool pass = false; int myk = 0;
        if (lane < cnt) {
            unsigned long long pc = g_cand[(size_t)gw * CAP + lane];
            if (__uint_as_float((unsigned)(pc >> 32)) < thr) {
                pass = true; myk = (int)(pc & 0xffffffffull);
            }
        }
        unsigned bal = __ballot_sync(0xffffffffu, pass);
        if (__popc(bal) == 1) {
            // single survivor: exact argmin is forced -> skip the chain entirely
            c = __shfl_sync(0xffffffffu, myk, __ffs(bal) - 1);
        } else {
            unsigned long long best = ~0ull;
            if (pass) {
                const float4* e4p = (const float4*)(emb + (size_t)myk * DD);
                float acc = 0.f;
#pragma unroll 4
                for (int i = 0; i < 64; i++) {      // exact ascending chain
                    float4 xv = x4p[i], ev = e4p[i];
                    acc = __fmaf_rn(2.0f * xv.x, ev.x, acc);
                    acc = __fmaf_rn(2.0f * xv.y, ev.y, acc);
                    acc = __fmaf_rn(2.0f * xv.z, ev.z, acc);
                    acc = __fmaf_rn(2.0f * xv.w, ev.w, acc);
                }
                float dd = __fadd_rn(__fadd_rn(xr, g_ee[myk]), -acc);
                best = (((unsigned long long)__float_as_uint(dd)) << 32) | (unsigned)myk;
            }
#pragma unroll
            for (int off = 16; off; off >>= 1) {
                unsigned long long o = __shfl_xor_sync(0xffffffffu, best, off);
                if (o < best) best = o;
            }
            c = (int)(best & 0xffffffffull);
        }
    } else {                                       // overflow: exact full scan
        unsigned long long best = ~0ull;
        for (int k = lane; k < KK; k += 32) {
            const float4* e4p = (const float4*)(emb + (size_t)k * DD);
            float acc = 0.f;
            for (int i = 0; i < 64; i++) {
                float4 xv = x4p[i], ev = e4p[i];
                acc = __fmaf_rn(2.0f * xv.x, ev.x, acc);
                acc = __fmaf_rn(2.0f * xv.y, ev.y, acc);
                acc = __fmaf_rn(2.0f * xv.z, ev.z, acc);
                acc = __fmaf_rn(2.0f * xv.w, ev.w, acc);
            }
            float dd = __fadd_rn(__fadd_rn(xr, g_ee[k]), -acc);
            unsigned long long pk =
                (((unsigned long long)__float_as_uint(dd)) << 32) | (unsigned)k;
            if (pk < best) best = pk;
        }
#pragma unroll
        for (int off = 16; off; off >>= 1) {
            unsigned long long o = __shfl_xor_sync(0xffffffffu, best, off);
            if (o < best) best = o;
        }
        c = (int)(best & 0xffffffffull);
    }
    if (lane == 0) {
        atomicAdd(&g_cnt[c], 1);
        out[OUT_IDX_BASE + gw] = (float)c;
    }

    // --- gather + straight-through output + MSE (identical rounding) ---
    const float m = mask[gw];
    const float4* e4p = (const float4*)(emb + (size_t)c * DD);
    float4* o4p = (float4*)(out + (size_t)gw * DD);
    double local = 0.0;
#pragma unroll
    for (int j = 0; j < 2; j++) {
        int i4 = lane + 32 * j;
        float4 e4 = e4p[i4], x4 = x4p[i4], o4;
        float qv, d1;
        qv = __fmul_rn(e4.x, m); d1 = __fadd_rn(qv, -x4.x); o4.x = __fadd_rn(x4.x, d1);
        local += (double)__fmul_rn(d1, d1);
        qv = __fmul_rn(e4.y, m); d1 = __fadd_rn(qv, -x4.y); o4.y = __fadd_rn(x4.y, d1);
        local += (double)__fmul_rn(d1, d1);
        qv = __fmul_rn(e4.z, m); d1 = __fadd_rn(qv, -x4.z); o4.z = __fadd_rn(x4.z, d1);
        local += (double)__fmul_rn(d1, d1);
        qv = __fmul_rn(e4.w, m); d1 = __fadd_rn(qv, -x4.w); o4.w = __fadd_rn(x4.w, d1);
        local += (double)__fmul_rn(d1, d1);
        o4p[i4] = o4;
    }
#pragma unroll
    for (int off = 16; off; off >>= 1) local += __shfl_xor_sync(0xffffffffu, local, off);
    if (lane == 0) sh[w] = local;
    __syncthreads();
    if (threadIdx.x == 0) {
        double s = 0.0;
        for (int i = 0; i < 8; i++) s += sh[i];
        atomicAdd(&g_sq, s);
    }
}

__global__ void k_final(float* __restrict__ out) {
    __shared__ double sh[8];
    double local = 0.0;
    for (int k = threadIdx.x; k < KK; k += blockDim.x) {
        float p = __fmul_rn((float)g_cnt[k], 1.0f / 32768.0f);
        local += (double)__fmul_rn(p, logf(__fadd_rn(p, 1e-8f)));
    }
#pragma unroll
    for (int off = 16; off; off >>= 1) local += __shfl_xor_sync(0xffffffffu, local, off);
    int lane = threadIdx.x & 31, w = threadIdx.x >> 5;
    if (lane == 0) sh[w] = local;
    __syncthreads();
    if (threadIdx.x == 0) {
        double H = 0.0;
        for (int i = 0; i < (int)(blockDim.x >> 5); i++) H += sh[i];
        double mse = g_sq / (double)(NN * DD);
        float ql = (float)mse;
        out[OUT_SCALAR_BASE + 0] = __fmul_rn(0.25f, ql);
        out[OUT_SCALAR_BASE + 1] = ql;
        out[OUT_SCALAR_BASE + 2] = expf(-(float)H);
    }
}

extern "C" void kernel_launch(void* const* d_in, const int* in_sizes, int n_in,
                              void* d_out, int out_size) {
    const float* x    = (const float*)d_in[0];
    const float* emb  = (const float*)d_in[1];
    const float* mask = (const float*)d_in[2];
    float* out = (float*)d_out;

    cudaFuncSetAttribute(k_mma, cudaFuncAttributeMaxDynamicSharedMemorySize, SMEM_DYN);

    k_prep<<<4608, 256>>>(x, emb);
    k_mma<<<NN / 128, 512, SMEM_DYN>>>();
    k_finish<<<NN / 8, 256>>>(x, emb, mask, out);
    k_final<<<1, 256>>>(out);
}